// round 1
// baseline (speedup 1.0000x reference)
#include <cuda_runtime.h>
#include <math.h>

#define N_ 8
#define C_ 256
#define H_ 64

// ---------------- scratch (static __device__; no allocation allowed) -------
__device__ float g_y4 [2048u*256*16];
__device__ float g_y8 [1800u*256*64];
__device__ float g_q4 [2048u*512*16];
__device__ float g_q8 [1800u*512*64];
__device__ float g_o4 [2048u*256*16];
__device__ float g_o8 [1800u*256*64];
__device__ float g_a4 [2048u*256*16];
__device__ float g_a8 [1800u*256*64];

// ---------------- stage 1: overlap-pool (2x2 mean) + dwconv3 + residual ----
// grid: (B tiles, C/G), block: G*K*K = 256
template<int K, int L, int G>
__global__ void pool_dw_kernel(const float* __restrict__ x,
                               const float* __restrict__ dpw,
                               const float* __restrict__ dpb,
                               float* __restrict__ yout)
{
    constexpr int KK = K*K;
    __shared__ float sp[G][K][K];
    int t   = blockIdx.x;
    int tid = threadIdx.x;
    int g = tid / KK;
    int s = tid - g*KK;
    int p = s / K, q = s - p*K;
    int n  = t / (L*L);
    int ab = t - n*(L*L);
    int a = ab / L, b = ab - a*L;
    int c = blockIdx.y * G + g;
    // pool row start within padded window: s0[p] = p*(K+2)/K  -> all pools 2-wide
    int s0p = (p*(K+2))/K;
    int s0q = (q*(K+2))/K;
    const float* xc = x + ((size_t)(n*C_ + c))*(H_*H_);
    int h0 = a*4 + s0p - 1;   // padded coord - 1 = x coord (edge clamp)
    int w0 = b*4 + s0q - 1;
    float acc = 0.f;
#pragma unroll
    for (int di = 0; di < 2; di++)
#pragma unroll
        for (int dj = 0; dj < 2; dj++) {
            int hh = min(max(h0+di, 0), H_-1);
            int ww = min(max(w0+dj, 0), H_-1);
            acc += xc[hh*H_ + ww];
        }
    acc *= 0.25f;
    sp[g][p][q] = acc;
    __syncthreads();
    const float* wc = dpw + c*9;
    float r = acc + dpb[c];               // residual + bias
#pragma unroll
    for (int u = 0; u < 3; u++)
#pragma unroll
        for (int v = 0; v < 3; v++) {
            int pp = p+u-1, qq = q+v-1;
            if (pp >= 0 && pp < K && qq >= 0 && qq < K)
                r += wc[u*3+v] * sp[g][pp][qq];
        }
    yout[((size_t)t*C_ + c)*KK + s] = r;
}

// ---------------- stages 2/4: per-tile GEMM  out[ODIM,KK] = W[ODIM,256]@y + b
// grid: B tiles, block 256. Each thread: OT x ST register tile.
template<int ODIM, int KK>
__global__ __launch_bounds__(256) void gemm_kernel(
    const float* __restrict__ w,
    const float* __restrict__ bias,
    const float* __restrict__ yin,
    float* __restrict__ out)
{
    constexpr int OT = ODIM/64;   // 8 (qkv) or 4 (proj)
    constexpr int ST = KK/4;      // 16 (K=8) or 4 (K=4)
    __shared__ float ych[16*KK];
    __shared__ float wch[16*ODIM];
    int tid = threadIdx.x;
    int t   = blockIdx.x;
    const float* ysrc = yin + (size_t)t * C_ * KK;
    int so = (tid >> 2) * OT;
    int sb = (tid & 3) * ST;
    float acc[OT][ST];
#pragma unroll
    for (int i = 0; i < OT; i++)
#pragma unroll
        for (int j = 0; j < ST; j++) acc[i][j] = 0.f;

    for (int c0 = 0; c0 < C_; c0 += 16) {
        // y chunk: 16*KK contiguous floats
        for (int i = tid; i < 16*KK; i += 256)
            ych[i] = ysrc[c0*KK + i];
        // w chunk: [cc][o] layout, float4 along c for coalesced global reads
        for (int i = tid; i < ODIM*4; i += 256) {
            int o  = i >> 2;
            int cq = (i & 3) << 2;
            float4 wv = *(const float4*)(w + (size_t)o*C_ + c0 + cq);
            wch[(cq+0)*ODIM + o] = wv.x;
            wch[(cq+1)*ODIM + o] = wv.y;
            wch[(cq+2)*ODIM + o] = wv.z;
            wch[(cq+3)*ODIM + o] = wv.w;
        }
        __syncthreads();
#pragma unroll 4
        for (int cc = 0; cc < 16; cc++) {
            float yf[ST], wf[OT];
#pragma unroll
            for (int j = 0; j < ST; j++) yf[j] = ych[cc*KK + sb + j];
#pragma unroll
            for (int i = 0; i < OT; i++) wf[i] = wch[cc*ODIM + so + i];
#pragma unroll
            for (int i = 0; i < OT; i++)
#pragma unroll
                for (int j = 0; j < ST; j++)
                    acc[i][j] += wf[i] * yf[j];
        }
        __syncthreads();
    }
#pragma unroll
    for (int i = 0; i < OT; i++) {
        float bv = bias[so+i];
#pragma unroll
        for (int j = 0; j < ST; j++)
            out[((size_t)t*ODIM + so+i)*KK + sb + j] = acc[i][j] + bv;
    }
}

// ---------------- stage 3: per (tile, head) attention + PE dwconv ---------
// grid: (B, 4), block 128
template<int K>
__global__ void attn_kernel(const float* __restrict__ qkv,
                            const float* __restrict__ pew,
                            const float* __restrict__ peb,
                            float* __restrict__ oout)
{
    constexpr int KK = K*K;
    __shared__ float sqkv[128*KK];     // q[0..32), k[32..64), v[64..128) rows
    __shared__ float satt[KK*KK];
    int t = blockIdx.x, h = blockIdx.y;
    int tid = threadIdx.x;
    const float* src = qkv + ((size_t)t*512 + h*128)*KK;
    for (int i = tid; i < 32*KK; i += 128)          // 128*KK/4 float4s
        ((float4*)sqkv)[i] = ((const float4*)src)[i];
    __syncthreads();

    const float scale = 0.17677669529663687f;       // 32^-0.5
    for (int idx = tid; idx < KK*KK; idx += 128) {
        int n = idx / KK, m = idx - (idx/KK)*KK;
        float d = 0.f;
#pragma unroll
        for (int dd = 0; dd < 32; dd++)
            d += sqkv[dd*KK + n] * sqkv[(32+dd)*KK + m];
        satt[n*KK+m] = d * scale;
    }
    __syncthreads();
    if (tid < KK) {
        int n = tid;
        float mx = -1e30f;
        for (int m = 0; m < KK; m++) mx = fmaxf(mx, satt[n*KK+m]);
        float sm = 0.f;
        for (int m = 0; m < KK; m++) { float e = __expf(satt[n*KK+m]-mx); satt[n*KK+m] = e; sm += e; }
        float inv = 1.f/sm;
        for (int m = 0; m < KK; m++) satt[n*KK+m] *= inv;
    }
    __syncthreads();
    for (int idx = tid; idx < 64*KK; idx += 128) {
        int d = idx / KK, n = idx - (idx/KK)*KK;
        const float* vrow = &sqkv[(64+d)*KK];
        const float* arow = &satt[n*KK];
        float acc = 0.f;
#pragma unroll 8
        for (int m = 0; m < KK; m++) acc += vrow[m]*arow[m];
        int c = h*64 + d;
        int p = n / K, q = n - (n/K)*K;
        float r = acc + peb[c];
        const float* wc = pew + c*9;
#pragma unroll
        for (int u = 0; u < 3; u++)
#pragma unroll
            for (int v = 0; v < 3; v++) {
                int pp = p+u-1, qq = q+v-1;
                if (pp >= 0 && pp < K && qq >= 0 && qq < K)
                    r += wc[u*3+v] * vrow[pp*K+qq];
            }
        oout[((size_t)t*256 + c)*KK + n] = r;
    }
}

// ---------------- stage 5: gather-fold + final average --------------------
// NOTE: reference reshapes the (N*L^2, C, K, K) proj output RAW to
// (N, C, K, K, L, L); so we read the flat buffer with that view's strides.
__global__ void combine_kernel(const float* __restrict__ x,
                               const float* __restrict__ a4,
                               const float* __restrict__ a8,
                               float* __restrict__ out)
{
    int idx = blockIdx.x*256 + threadIdx.x;
    if (idx >= N_*C_*H_*H_) return;
    int w = idx & 63;
    int h = (idx >> 6) & 63;
    int c = (idx >> 12) & 255;
    int n = idx >> 20;
    float xv = x[idx];
    // K=4, L=16: non-overlapping, count 1
    {
        int p = h & 3, lh = h >> 2, q = w & 3, lw = w >> 2;
        xv += a4[(size_t)n*(256*16*256) + ((c*4+p)*4+q)*256 + lh*16 + lw];
    }
    // K=8, L=15: up to 2 contributors per axis
    float v8 = 0.f; int cnt = 0;
    int l1h = h >> 2, l1w = w >> 2;
#pragma unroll
    for (int dh = 0; dh < 2; dh++) {
        int lh = l1h - dh;
        if (lh < 0 || lh > 14) continue;
        int p = h - 4*lh;                       // in [0,8)
#pragma unroll
        for (int dw = 0; dw < 2; dw++) {
            int lw = l1w - dw;
            if (lw < 0 || lw > 14) continue;
            int q = w - 4*lw;
            v8 += a8[(size_t)n*(256*64*225) + ((c*8+p)*8+q)*225 + lh*15 + lw];
            cnt++;
        }
    }
    out[idx] = (xv + v8 * (1.f/(float)cnt)) * (1.f/3.f);
}

// ---------------------------------------------------------------------------
extern "C" void kernel_launch(void* const* d_in, const int* in_sizes, int n_in,
                              void* d_out, int out_size)
{
    const float* x     = (const float*)d_in[0];
    const float* qkvw  = (const float*)d_in[1];
    const float* qkvb  = (const float*)d_in[2];
    const float* projw = (const float*)d_in[3];
    const float* projb = (const float*)d_in[4];
    const float* apew  = (const float*)d_in[5];
    const float* apeb  = (const float*)d_in[6];
    const float* dpew  = (const float*)d_in[7];
    const float* dpeb  = (const float*)d_in[8];
    float* out = (float*)d_out;

    float *y4,*y8,*q4,*q8,*o4,*o8,*a4,*a8;
    cudaGetSymbolAddress((void**)&y4, g_y4);
    cudaGetSymbolAddress((void**)&y8, g_y8);
    cudaGetSymbolAddress((void**)&q4, g_q4);
    cudaGetSymbolAddress((void**)&q8, g_q8);
    cudaGetSymbolAddress((void**)&o4, g_o4);
    cudaGetSymbolAddress((void**)&o8, g_o8);
    cudaGetSymbolAddress((void**)&a4, g_a4);
    cudaGetSymbolAddress((void**)&a8, g_a8);

    // K=4: L=16, B=2048 ; K=8: L=15, B=1800
    pool_dw_kernel<4,16,16><<<dim3(2048,16), 256>>>(x, dpew, dpeb, y4);
    pool_dw_kernel<8,15, 4><<<dim3(1800,64), 256>>>(x, dpew, dpeb, y8);

    gemm_kernel<512,16><<<2048,256>>>(qkvw, qkvb, y4, q4);
    gemm_kernel<512,64><<<1800,256>>>(qkvw, qkvb, y8, q8);

    attn_kernel<4><<<dim3(2048,4),128>>>(q4, apew, apeb, o4);
    attn_kernel<8><<<dim3(1800,4),128>>>(q8, apew, apeb, o8);

    gemm_kernel<256,16><<<2048,256>>>(projw, projb, o4, a4);
    gemm_kernel<256,64><<<1800,256>>>(projw, projb, o8, a8);

    combine_kernel<<<(N_*C_*H_*H_ + 255)/256, 256>>>(x, a4, a8, out);
}

// round 6
// speedup vs baseline: 3.3217x; 3.3217x over previous
#include <cuda_runtime.h>
#include <cstdint>

#define N_ 8
#define C_ 256
#define H_ 64
#define NCOL 147968            // 2048*16 + 1800*64
#define COL8_BASE 32768

// ---------------- scratch ---------------------------------------------------
__device__ float g_y [(size_t)NCOL*256];        // y_all [col][256]
__device__ float g_o [(size_t)NCOL*256];        // attn out [col][256]
__device__ float g_q4[(size_t)2048*512*16];     // qkv K=4 [t][512][16]
__device__ float g_q8[(size_t)1800*512*64];     // qkv K=8 [t][512][64]
__device__ float g_a4[(size_t)2048*256*16];
__device__ float g_a8[(size_t)1800*256*64];

// ---------------- helpers ----------------------------------------------------
__device__ __forceinline__ uint32_t f2tf32(float f) {
    uint32_t r;
    asm("cvt.rna.tf32.f32 %0, %1;" : "=r"(r) : "f"(f));
    return r;
}
__device__ __forceinline__ void mma_m16n8k8(float* c, const uint32_t* a, const uint32_t* b) {
    asm volatile("mma.sync.aligned.m16n8k8.row.col.f32.tf32.tf32.f32 "
        "{%0,%1,%2,%3}, {%4,%5,%6,%7}, {%8,%9}, {%0,%1,%2,%3};"
        : "+f"(c[0]), "+f"(c[1]), "+f"(c[2]), "+f"(c[3])
        : "r"(a[0]), "r"(a[1]), "r"(a[2]), "r"(a[3]), "r"(b[0]), "r"(b[1]));
}

// ---------------- stage 1: pool(2x2 mean) + dwconv3 + residual -> y_all -----
// layout out: y_all[col][256], col = (K==4 ? t*16+s : COL8_BASE + t*64+s)
template<int K, int L, int G, int TPB>
__global__ __launch_bounds__(TPB) void pool_dw_kernel(
    const float* __restrict__ x, const float* __restrict__ dpw,
    const float* __restrict__ dpb, float* __restrict__ yall)
{
    constexpr int KK = K*K;
    __shared__ float sp[KK*G];
    int t = blockIdx.x, tid = threadIdx.x;
    int g = tid % G, s = tid / G;
    int p = s / K, q = s % K;
    int n = t / (L*L);
    int ab = t - n*(L*L);
    int a = ab / L, b = ab % L;
    int c = blockIdx.y * G + g;
    int s0p = (p*(K+2))/K, s0q = (q*(K+2))/K;
    const float* xc = x + ((size_t)(n*C_ + c))*(H_*H_);
    int h0 = a*4 + s0p - 1, w0 = b*4 + s0q - 1;
    float acc = 0.f;
#pragma unroll
    for (int di = 0; di < 2; di++)
#pragma unroll
        for (int dj = 0; dj < 2; dj++) {
            int hh = min(max(h0+di, 0), H_-1);
            int ww = min(max(w0+dj, 0), H_-1);
            acc += xc[hh*H_ + ww];
        }
    acc *= 0.25f;
    sp[s*G + g] = acc;
    __syncthreads();
    const float* wc = dpw + c*9;
    float r = acc + dpb[c];
#pragma unroll
    for (int u = 0; u < 3; u++)
#pragma unroll
        for (int v = 0; v < 3; v++) {
            int pp = p+u-1, qq = q+v-1;
            if (pp >= 0 && pp < K && qq >= 0 && qq < K)
                r += wc[u*3+v] * sp[(pp*K+qq)*G + g];
        }
    int colbase = (K == 4) ? t*16 : COL8_BASE + t*64;
    yall[(size_t)(colbase + s)*256 + c] = r;
}

// ---------------- tf32 mma.sync GEMM ----------------------------------------
// D[M x NCOL] = W[M,256] @ Y^T (+bias), Y stored [col][256] (K-major).
// CTA tile 128x128, K=256 in 16 chunks of 16, double buffered.
// 8 warps: warpM = wid&1 (2 x 64 rows), warpN = wid>>1 (4 x 32 cols).
// smem row stride 20 words -> conflict-free quad access for mma fragments.
#define SROW 20
__global__ __launch_bounds__(256) void mma_gemm(
    const float* __restrict__ W, const float* __restrict__ bias,
    const float* __restrict__ Bm,
    float* __restrict__ out4, float* __restrict__ out8, int OD)
{
    __shared__ uint32_t As[2][128*SROW];
    __shared__ uint32_t Bs[2][128*SROW];
    int tid = threadIdx.x, lane = tid & 31, wid = tid >> 5;
    int warpM = wid & 1, warpN = wid >> 1;
    int mrow0 = blockIdx.x * 128, col0 = blockIdx.y * 128;
    const float* Ap = W  + (size_t)mrow0 * 256;
    const float* Bp = Bm + (size_t)col0  * 256;

    int r     = tid >> 1;            // 0..127
    int halfo = (tid & 1) * 8;       // 0 or 8 (floats within 16-wide chunk)

    float acc[4][4][4];
#pragma unroll
    for (int mt = 0; mt < 4; mt++)
#pragma unroll
        for (int nt = 0; nt < 4; nt++)
#pragma unroll
            for (int i = 0; i < 4; i++) acc[mt][nt][i] = 0.f;

    // prologue: chunk 0 -> buf 0
    {
        float4 a0 = *(const float4*)(Ap + (size_t)r*256 + halfo);
        float4 a1 = *(const float4*)(Ap + (size_t)r*256 + halfo + 4);
        float4 b0 = *(const float4*)(Bp + (size_t)r*256 + halfo);
        float4 b1 = *(const float4*)(Bp + (size_t)r*256 + halfo + 4);
        uint32_t* pa = &As[0][r*SROW + halfo];
        uint32_t* pb = &Bs[0][r*SROW + halfo];
        pa[0]=f2tf32(a0.x); pa[1]=f2tf32(a0.y); pa[2]=f2tf32(a0.z); pa[3]=f2tf32(a0.w);
        pa[4]=f2tf32(a1.x); pa[5]=f2tf32(a1.y); pa[6]=f2tf32(a1.z); pa[7]=f2tf32(a1.w);
        pb[0]=f2tf32(b0.x); pb[1]=f2tf32(b0.y); pb[2]=f2tf32(b0.z); pb[3]=f2tf32(b0.w);
        pb[4]=f2tf32(b1.x); pb[5]=f2tf32(b1.y); pb[6]=f2tf32(b1.z); pb[7]=f2tf32(b1.w);
    }
    __syncthreads();

    int rowA = warpM*64 + (lane >> 2);
    int rowB = warpN*32 + (lane >> 2);
    int kq   = lane & 3;

    for (int kc = 0; kc < 16; kc++) {
        int buf = kc & 1;
        float4 a0, a1, b0, b1;
        if (kc < 15) {
            const float* ap = Ap + (size_t)r*256 + (kc+1)*16 + halfo;
            const float* bp = Bp + (size_t)r*256 + (kc+1)*16 + halfo;
            a0 = *(const float4*)(ap);     a1 = *(const float4*)(ap + 4);
            b0 = *(const float4*)(bp);     b1 = *(const float4*)(bp + 4);
        }
#pragma unroll
        for (int ks = 0; ks < 2; ks++) {
            int kb = ks*8 + kq;
            uint32_t af[4][4], bf[4][2];
#pragma unroll
            for (int mt = 0; mt < 4; mt++) {
                const uint32_t* base = &As[buf][(rowA + mt*16)*SROW + kb];
                af[mt][0] = base[0];
                af[mt][1] = base[8*SROW];
                af[mt][2] = base[4];
                af[mt][3] = base[8*SROW + 4];
            }
#pragma unroll
            for (int nt = 0; nt < 4; nt++) {
                const uint32_t* base = &Bs[buf][(rowB + nt*8)*SROW + kb];
                bf[nt][0] = base[0];
                bf[nt][1] = base[4];
            }
#pragma unroll
            for (int mt = 0; mt < 4; mt++)
#pragma unroll
                for (int nt = 0; nt < 4; nt++)
                    mma_m16n8k8(acc[mt][nt], af[mt], bf[nt]);
        }
        if (kc < 15) {
            uint32_t* pa = &As[buf^1][r*SROW + halfo];
            uint32_t* pb = &Bs[buf^1][r*SROW + halfo];
            pa[0]=f2tf32(a0.x); pa[1]=f2tf32(a0.y); pa[2]=f2tf32(a0.z); pa[3]=f2tf32(a0.w);
            pa[4]=f2tf32(a1.x); pa[5]=f2tf32(a1.y); pa[6]=f2tf32(a1.z); pa[7]=f2tf32(a1.w);
            pb[0]=f2tf32(b0.x); pb[1]=f2tf32(b0.y); pb[2]=f2tf32(b0.z); pb[3]=f2tf32(b0.w);
            pb[4]=f2tf32(b1.x); pb[5]=f2tf32(b1.y); pb[6]=f2tf32(b1.z); pb[7]=f2tf32(b1.w);
        }
        __syncthreads();
    }

    // epilogue: bias + store to per-tile layouts (float2 along spatial dim)
#pragma unroll
    for (int mt = 0; mt < 4; mt++) {
        int m0 = mrow0 + warpM*64 + mt*16 + (lane >> 2);
        float bv0 = bias[m0], bv1 = bias[m0 + 8];
#pragma unroll
        for (int nt = 0; nt < 4; nt++) {
            int coln = col0 + warpN*32 + nt*8 + (lane & 3)*2;
            float2 v0 = make_float2(acc[mt][nt][0] + bv0, acc[mt][nt][1] + bv0);
            float2 v1 = make_float2(acc[mt][nt][2] + bv1, acc[mt][nt][3] + bv1);
            if (coln < COL8_BASE) {
                int t0 = coln >> 4, s = coln & 15;
                *(float2*)(out4 + ((size_t)t0*OD + m0    )*16 + s) = v0;
                *(float2*)(out4 + ((size_t)t0*OD + m0 + 8)*16 + s) = v1;
            } else {
                int t0 = (coln - COL8_BASE) >> 6, s = coln & 63;
                *(float2*)(out8 + ((size_t)t0*OD + m0    )*64 + s) = v0;
                *(float2*)(out8 + ((size_t)t0*OD + m0 + 8)*64 + s) = v1;
            }
        }
    }
}

// ---------------- stage 3: attention + PE dwconv -> o_all[col][256] --------
template<int K, int LOG2KK>
__global__ __launch_bounds__(128) void attn_kernel(
    const float* __restrict__ qkv, const float* __restrict__ pew,
    const float* __restrict__ peb, float* __restrict__ oall)
{
    constexpr int KK = K*K;
    constexpr int KKP = KK + 1;
    extern __shared__ float sm[];
    float* sqkv = sm;                 // [128][KKP]
    float* satt = sm + 128*KKP;       // [KK][KKP]
    int t = blockIdx.x, h = blockIdx.y, tid = threadIdx.x;
    const float* src = qkv + ((size_t)t*512 + h*128)*KK;
    for (int i4 = tid; i4 < 128*(KK/4); i4 += 128) {
        int r = i4 / (KK/4);
        int c4 = (i4 % (KK/4)) * 4;
        float4 v = ((const float4*)src)[i4];
        sqkv[r*KKP + c4+0] = v.x; sqkv[r*KKP + c4+1] = v.y;
        sqkv[r*KKP + c4+2] = v.z; sqkv[r*KKP + c4+3] = v.w;
    }
    __syncthreads();

    const float scale = 0.17677669529663687f;     // 32^-0.5
    for (int idx = tid; idx < KK*KK; idx += 128) {
        int m = idx & (KK-1);
        int n = idx >> LOG2KK;
        float d = 0.f;
#pragma unroll
        for (int dd = 0; dd < 32; dd++)
            d += sqkv[dd*KKP + n] * sqkv[(32+dd)*KKP + m];
        satt[n*KKP + m] = d * scale;
    }
    __syncthreads();
    if (tid < KK) {
        float* row = &satt[tid*KKP];
        float mx = -1e30f;
        for (int m = 0; m < KK; m++) mx = fmaxf(mx, row[m]);
        float smv = 0.f;
        for (int m = 0; m < KK; m++) { float e = __expf(row[m]-mx); row[m] = e; smv += e; }
        float inv = 1.f/smv;
        for (int m = 0; m < KK; m++) row[m] *= inv;
    }
    __syncthreads();
    int colbase = (K == 4) ? t*16 : COL8_BASE + t*64;
    for (int idx = tid; idx < 64*KK; idx += 128) {
        int d = idx & 63;
        int n = idx >> 6;
        const float* vrow = &sqkv[(64+d)*KKP];
        const float* arow = &satt[n*KKP];
        float acc = 0.f;
#pragma unroll 8
        for (int m = 0; m < KK; m++) acc += vrow[m]*arow[m];
        int c = h*64 + d;
        int p = n / K, q = n % K;
        float r = acc + peb[c];
        const float* wc = pew + c*9;
#pragma unroll
        for (int u = 0; u < 3; u++)
#pragma unroll
            for (int v = 0; v < 3; v++) {
                int pp = p+u-1, qq = q+v-1;
                if (pp >= 0 && pp < K && qq >= 0 && qq < K)
                    r += wc[u*3+v] * vrow[pp*K+qq];
            }
        oall[(size_t)(colbase + n)*256 + c] = r;
    }
}

// ---------------- stage 5: gather-fold + final average ----------------------
__global__ void combine_kernel(const float* __restrict__ x,
                               const float* __restrict__ a4,
                               const float* __restrict__ a8,
                               float* __restrict__ out)
{
    int idx = blockIdx.x*256 + threadIdx.x;
    if (idx >= N_*C_*H_*H_) return;
    int w = idx & 63;
    int h = (idx >> 6) & 63;
    int c = (idx >> 12) & 255;
    int n = idx >> 20;
    float xv = x[idx];
    {
        int p = h & 3, lh = h >> 2, q = w & 3, lw = w >> 2;
        xv += a4[(size_t)n*(256*16*256) + ((c*4+p)*4+q)*256 + lh*16 + lw];
    }
    float v8 = 0.f; int cnt = 0;
    int l1h = h >> 2, l1w = w >> 2;
#pragma unroll
    for (int dh = 0; dh < 2; dh++) {
        int lh = l1h - dh;
        if (lh < 0 || lh > 14) continue;
        int p = h - 4*lh;
#pragma unroll
        for (int dw = 0; dw < 2; dw++) {
            int lw = l1w - dw;
            if (lw < 0 || lw > 14) continue;
            int q = w - 4*lw;
            v8 += a8[(size_t)n*(256*64*225) + ((c*8+p)*8+q)*225 + lh*15 + lw];
            cnt++;
        }
    }
    out[idx] = (xv + v8 * (1.f/(float)cnt)) * (1.f/3.f);
}

// ---------------------------------------------------------------------------
extern "C" void kernel_launch(void* const* d_in, const int* in_sizes, int n_in,
                              void* d_out, int out_size)
{
    const float* x     = (const float*)d_in[0];
    const float* qkvw  = (const float*)d_in[1];
    const float* qkvb  = (const float*)d_in[2];
    const float* projw = (const float*)d_in[3];
    const float* projb = (const float*)d_in[4];
    const float* apew  = (const float*)d_in[5];
    const float* apeb  = (const float*)d_in[6];
    const float* dpew  = (const float*)d_in[7];
    const float* dpeb  = (const float*)d_in[8];
    float* out = (float*)d_out;

    float *yall,*oall,*q4,*q8,*a4,*a8;
    cudaGetSymbolAddress((void**)&yall, g_y);
    cudaGetSymbolAddress((void**)&oall, g_o);
    cudaGetSymbolAddress((void**)&q4,   g_q4);
    cudaGetSymbolAddress((void**)&q8,   g_q8);
    cudaGetSymbolAddress((void**)&a4,   g_a4);
    cudaGetSymbolAddress((void**)&a8,   g_a8);

    int attn8_smem = (128*65 + 64*65) * sizeof(float);
    cudaFuncSetAttribute(attn_kernel<8,6>, cudaFuncAttributeMaxDynamicSharedMemorySize, attn8_smem);
    int attn4_smem = (128*17 + 16*17) * sizeof(float);

    pool_dw_kernel<4,16,16,256><<<dim3(2048,16), 256>>>(x, dpew, dpeb, yall);
    pool_dw_kernel<8,15, 8,512><<<dim3(1800,32), 512>>>(x, dpew, dpeb, yall);

    // qkv: M=512 -> grid.x=4 ; NCOL/128 = 1156 col tiles
    mma_gemm<<<dim3(4, NCOL/128), 256>>>(qkvw, qkvb, yall, q4, q8, 512);

    attn_kernel<4,4><<<dim3(2048,4), 128, attn4_smem>>>(q4, apew, apeb, oall);
    attn_kernel<8,6><<<dim3(1800,4), 128, attn8_smem>>>(q8, apew, apeb, oall);

    // proj: M=256 -> grid.x=2
    mma_gemm<<<dim3(2, NCOL/128), 256>>>(projw, projb, oall, a4, a8, 256);

    combine_kernel<<<(N_*C_*H_*H_ + 255)/256, 256>>>(x, a4, a8, out);
}

// round 7
// speedup vs baseline: 3.3329x; 1.0034x over previous
#include <cuda_runtime.h>
#include <cstdint>

#define N_ 8
#define C_ 256
#define H_ 64
#define NCOL 147968            // 2048*16 + 1800*64
#define COL8_BASE 32768

// ---------------- scratch ---------------------------------------------------
__device__ float g_y [(size_t)256*NCOL];        // y_all [c][col]
__device__ float g_o [(size_t)256*NCOL];        // attn out [c][col]
__device__ float g_q4[(size_t)2048*512*16];     // qkv K=4 [t][512][16]
__device__ float g_q8[(size_t)1800*512*64];     // qkv K=8 [t][512][64]
__device__ float g_a4[(size_t)2048*256*16];
__device__ float g_a8[(size_t)1800*256*64];

// ---------------- helpers ----------------------------------------------------
__device__ __forceinline__ uint32_t f2tf32(float f) {
    uint32_t r;
    asm("cvt.rna.tf32.f32 %0, %1;" : "=r"(r) : "f"(f));
    return r;
}
__device__ __forceinline__ void mma_m16n8k8(float* c, const uint32_t* a, const uint32_t* b) {
    asm volatile("mma.sync.aligned.m16n8k8.row.col.f32.tf32.tf32.f32 "
        "{%0,%1,%2,%3}, {%4,%5,%6,%7}, {%8,%9}, {%0,%1,%2,%3};"
        : "+f"(c[0]), "+f"(c[1]), "+f"(c[2]), "+f"(c[3])
        : "r"(a[0]), "r"(a[1]), "r"(a[2]), "r"(a[3]), "r"(b[0]), "r"(b[1]));
}

// ---------------- stage 1a: pool+dwconv K=4 -> y_all[c][col] ----------------
// grid (a=16, n=8, cg=16), block 256. Row-strip: rows a*4-1 .. a*4+5 (7)
__global__ __launch_bounds__(256) void pool4_kernel(
    const float* __restrict__ x, const float* __restrict__ dpw,
    const float* __restrict__ dpb, float* __restrict__ yall)
{
    __shared__ float sx[16*448];      // [c][7][64]
    __shared__ float sp[16*272];      // [c][b(16) stride 17][s(16)]
    int a = blockIdx.x, n = blockIdx.y, cbase = blockIdx.z * 16;
    int tid = threadIdx.x;
    for (int i4 = tid; i4 < 1792; i4 += 256) {
        int c = i4 / 112, rem = i4 - c*112;
        int hh = rem >> 4, w4 = (rem & 15) << 2;
        int gh = min(max(a*4 - 1 + hh, 0), 63);
        float4 v = *(const float4*)(x + (((size_t)(n*C_ + cbase + c)*64 + gh) << 6) + w4);
        *(float4*)(sx + c*448 + hh*64 + w4) = v;
    }
    __syncthreads();
    {
        int c = tid >> 4, b = tid & 15;
        const float* sxc = sx + c*448;
#pragma unroll
        for (int s = 0; s < 16; s++) {
            int p = s >> 2, q = s & 3;
            int rl = (p*6) >> 2;                 // s0p
            int w0 = b*4 + ((q*6) >> 2) - 1;
            int wa = min(max(w0, 0), 63), wb = min(max(w0+1, 0), 63);
            float acc = 0.25f * (sxc[rl*64 + wa] + sxc[rl*64 + wb] +
                                 sxc[(rl+1)*64 + wa] + sxc[(rl+1)*64 + wb]);
            sp[c*272 + b*17 + s] = acc;
        }
    }
    __syncthreads();
    {
        int c = tid >> 4, b = tid & 15;
        const float* wc = dpw + (cbase + c)*9;
        float bv = dpb[cbase + c];
        const float* spc = sp + c*272 + b*17;
        float outv[16];
#pragma unroll
        for (int s = 0; s < 16; s++) {
            int p = s >> 2, q = s & 3;
            float r = spc[s] + bv;
#pragma unroll
            for (int u = 0; u < 3; u++)
#pragma unroll
                for (int v = 0; v < 3; v++) {
                    int pp = p+u-1, qq = q+v-1;
                    if (pp >= 0 && pp < 4 && qq >= 0 && qq < 4)
                        r += wc[u*3+v] * spc[pp*4+qq];
                }
            outv[s] = r;
        }
        float* dst = yall + (size_t)(cbase + c)*NCOL + (((n<<8) + (a<<4) + b) << 4);
#pragma unroll
        for (int j = 0; j < 4; j++)
            *(float4*)(dst + j*4) = make_float4(outv[j*4], outv[j*4+1], outv[j*4+2], outv[j*4+3]);
    }
}

// ---------------- stage 1b: pool+dwconv K=8 ---------------------------------
// grid (a=15, n=8, cg=64), block 256. Rows a*4-1 .. a*4+9 (11)
__global__ __launch_bounds__(256) void pool8_kernel(
    const float* __restrict__ x, const float* __restrict__ dpw,
    const float* __restrict__ dpb, float* __restrict__ yall)
{
    __shared__ float sx[4*704];       // [c][11][64]
    __shared__ float sp[4*960];       // [c][b(15)][s(64)]
    int a = blockIdx.x, n = blockIdx.y, cbase = blockIdx.z * 4;
    int tid = threadIdx.x;
    for (int i4 = tid; i4 < 704; i4 += 256) {
        int c = i4 / 176, rem = i4 - c*176;
        int hh = rem >> 4, w4 = (rem & 15) << 2;
        int gh = min(max(a*4 - 1 + hh, 0), 63);
        float4 v = *(const float4*)(x + (((size_t)(n*C_ + cbase + c)*64 + gh) << 6) + w4);
        *(float4*)(sx + c*704 + hh*64 + w4) = v;
    }
    __syncthreads();
    {
        int c = tid >> 6, s = tid & 63;
        int p = s >> 3, q = s & 7;
        int rl = (p*10) >> 3;
        int cq = (q*10) >> 3;
        const float* sxc = sx + c*704;
#pragma unroll
        for (int b = 0; b < 15; b++) {
            int w0 = b*4 + cq - 1;
            int wa = min(max(w0, 0), 63), wb = min(max(w0+1, 0), 63);
            sp[c*960 + b*64 + s] = 0.25f * (sxc[rl*64 + wa] + sxc[rl*64 + wb] +
                                            sxc[(rl+1)*64 + wa] + sxc[(rl+1)*64 + wb]);
        }
    }
    __syncthreads();
    {
        int c = tid >> 6, s = tid & 63;
        int p = s >> 3, q = s & 7;
        const float* wc = dpw + (cbase + c)*9;
        float bv = dpb[cbase + c];
        float* dst = yall + (size_t)(cbase + c)*NCOL + COL8_BASE + ((size_t)(n*225 + a*15) << 6) + s;
#pragma unroll
        for (int b = 0; b < 15; b++) {
            const float* spc = sp + c*960 + b*64;
            float r = spc[s] + bv;
#pragma unroll
            for (int u = 0; u < 3; u++)
#pragma unroll
                for (int v = 0; v < 3; v++) {
                    int pp = p+u-1, qq = q+v-1;
                    if (pp >= 0 && pp < 8 && qq >= 0 && qq < 8)
                        r += wc[u*3+v] * spc[pp*8+qq];
                }
            dst[b << 6] = r;
        }
    }
}

// ---------------- tf32 mma.sync GEMM ----------------------------------------
// D[M x NCOL] = W[M,256] @ Y (+bias), Y stored [c][col]. CTA 128x128.
#define SROW 20
#define BROW 132
__global__ __launch_bounds__(256) void mma_gemm(
    const float* __restrict__ W, const float* __restrict__ bias,
    const float* __restrict__ Bm,
    float* __restrict__ out4, float* __restrict__ out8, int OD)
{
    __shared__ uint32_t As[2][128*SROW];
    __shared__ uint32_t Bsk[2][16*BROW];
    int tid = threadIdx.x, lane = tid & 31, wid = tid >> 5;
    int warpM = wid & 1, warpN = wid >> 1;
    int mrow0 = blockIdx.x * 128, col0 = blockIdx.y * 128;
    const float* Ap = W + (size_t)mrow0 * 256;

    int r     = tid >> 1;
    int halfo = (tid & 1) * 8;

    float acc[4][4][4];
#pragma unroll
    for (int mt = 0; mt < 4; mt++)
#pragma unroll
        for (int nt = 0; nt < 4; nt++)
#pragma unroll
            for (int i = 0; i < 4; i++) acc[mt][nt][i] = 0.f;

    // prologue: chunk 0 -> buf 0
    {
        float4 a0 = *(const float4*)(Ap + (size_t)r*256 + halfo);
        float4 a1 = *(const float4*)(Ap + (size_t)r*256 + halfo + 4);
        uint32_t* pa = &As[0][r*SROW + halfo];
        pa[0]=f2tf32(a0.x); pa[1]=f2tf32(a0.y); pa[2]=f2tf32(a0.z); pa[3]=f2tf32(a0.w);
        pa[4]=f2tf32(a1.x); pa[5]=f2tf32(a1.y); pa[6]=f2tf32(a1.z); pa[7]=f2tf32(a1.w);
#pragma unroll
        for (int ii = 0; ii < 2; ii++) {
            int i = tid + ii*256;
            int k = i >> 5, c4 = (i & 31) << 2;
            float4 v = *(const float4*)(Bm + (size_t)k*NCOL + col0 + c4);
            uint32_t* pb = &Bsk[0][k*BROW + c4];
            pb[0]=f2tf32(v.x); pb[1]=f2tf32(v.y); pb[2]=f2tf32(v.z); pb[3]=f2tf32(v.w);
        }
    }
    __syncthreads();

    int rowA = warpM*64 + (lane >> 2);
    int rowB = warpN*32 + (lane >> 2);
    int kq   = lane & 3;

    for (int kc = 0; kc < 16; kc++) {
        int buf = kc & 1;
        float4 a0, a1, nb0, nb1;
        if (kc < 15) {
            const float* ap = Ap + (size_t)r*256 + (kc+1)*16 + halfo;
            a0 = *(const float4*)(ap);     a1 = *(const float4*)(ap + 4);
            int i0 = tid,       k0 = i0 >> 5, c40 = (i0 & 31) << 2;
            int i1 = tid + 256, k1 = i1 >> 5, c41 = (i1 & 31) << 2;
            nb0 = *(const float4*)(Bm + (size_t)((kc+1)*16 + k0)*NCOL + col0 + c40);
            nb1 = *(const float4*)(Bm + (size_t)((kc+1)*16 + k1)*NCOL + col0 + c41);
        }
#pragma unroll
        for (int ks = 0; ks < 2; ks++) {
            int kb = ks*8 + kq;
            uint32_t af[4][4], bf[4][2];
#pragma unroll
            for (int mt = 0; mt < 4; mt++) {
                const uint32_t* base = &As[buf][(rowA + mt*16)*SROW + kb];
                af[mt][0] = base[0];
                af[mt][1] = base[8*SROW];
                af[mt][2] = base[4];
                af[mt][3] = base[8*SROW + 4];
            }
#pragma unroll
            for (int nt = 0; nt < 4; nt++) {
                bf[nt][0] = Bsk[buf][kb*BROW + rowB + nt*8];
                bf[nt][1] = Bsk[buf][(kb+4)*BROW + rowB + nt*8];
            }
#pragma unroll
            for (int mt = 0; mt < 4; mt++)
#pragma unroll
                for (int nt = 0; nt < 4; nt++)
                    mma_m16n8k8(acc[mt][nt], af[mt], bf[nt]);
        }
        if (kc < 15) {
            uint32_t* pa = &As[buf^1][r*SROW + halfo];
            pa[0]=f2tf32(a0.x); pa[1]=f2tf32(a0.y); pa[2]=f2tf32(a0.z); pa[3]=f2tf32(a0.w);
            pa[4]=f2tf32(a1.x); pa[5]=f2tf32(a1.y); pa[6]=f2tf32(a1.z); pa[7]=f2tf32(a1.w);
            int i0 = tid,       k0 = i0 >> 5, c40 = (i0 & 31) << 2;
            int i1 = tid + 256, k1 = i1 >> 5, c41 = (i1 & 31) << 2;
            uint32_t* pb0 = &Bsk[buf^1][k0*BROW + c40];
            pb0[0]=f2tf32(nb0.x); pb0[1]=f2tf32(nb0.y); pb0[2]=f2tf32(nb0.z); pb0[3]=f2tf32(nb0.w);
            uint32_t* pb1 = &Bsk[buf^1][k1*BROW + c41];
            pb1[0]=f2tf32(nb1.x); pb1[1]=f2tf32(nb1.y); pb1[2]=f2tf32(nb1.z); pb1[3]=f2tf32(nb1.w);
        }
        __syncthreads();
    }

#pragma unroll
    for (int mt = 0; mt < 4; mt++) {
        int m0 = mrow0 + warpM*64 + mt*16 + (lane >> 2);
        float bv0 = bias[m0], bv1 = bias[m0 + 8];
#pragma unroll
        for (int nt = 0; nt < 4; nt++) {
            int coln = col0 + warpN*32 + nt*8 + (lane & 3)*2;
            float2 v0 = make_float2(acc[mt][nt][0] + bv0, acc[mt][nt][1] + bv0);
            float2 v1 = make_float2(acc[mt][nt][2] + bv1, acc[mt][nt][3] + bv1);
            if (coln < COL8_BASE) {
                int t0 = coln >> 4, s = coln & 15;
                *(float2*)(out4 + ((size_t)t0*OD + m0    )*16 + s) = v0;
                *(float2*)(out4 + ((size_t)t0*OD + m0 + 8)*16 + s) = v1;
            } else {
                int t0 = (coln - COL8_BASE) >> 6, s = coln & 63;
                *(float2*)(out8 + ((size_t)t0*OD + m0    )*64 + s) = v0;
                *(float2*)(out8 + ((size_t)t0*OD + m0 + 8)*64 + s) = v1;
            }
        }
    }
}

// ---------------- stage 3a: attention K=8 (tensor cores) --------------------
// grid (1800, 4), 128 thr (4 warps; warp w owns S-rows w*16..w*16+15)
__global__ __launch_bounds__(128) void attn8_mma(
    const float* __restrict__ q8, const float* __restrict__ pew,
    const float* __restrict__ peb, float* __restrict__ oall)
{
    extern __shared__ float sm8[];
    float* sqkv = sm8;                 // [128][68] (tf32 bits)
    float* sSO  = sm8 + 128*68;        // [64][68]
    float* swt  = sSO + 64*68;         // [64][10]
    uint32_t* uq = (uint32_t*)sqkv;
    uint32_t* uS = (uint32_t*)sSO;
    int t = blockIdx.x, h = blockIdx.y, tid = threadIdx.x;
    int lane = tid & 31, w = tid >> 5, r = lane >> 2, qd = lane & 3;

    const float4* src = (const float4*)(q8 + ((size_t)t*512 + h*128)*64);
    for (int i4 = tid; i4 < 2048; i4 += 128) {
        int row = i4 >> 4, c4 = (i4 & 15) << 2;
        float4 v = src[i4];
        uint32_t* p = &uq[row*68 + c4];
        p[0]=f2tf32(v.x); p[1]=f2tf32(v.y); p[2]=f2tf32(v.z); p[3]=f2tf32(v.w);
    }
    for (int i = tid; i < 576; i += 128) {
        int ch = i / 9, k = i - ch*9;
        swt[ch*10 + k] = pew[(h*64+ch)*9 + k];
    }
    if (tid < 64) swt[tid*10+9] = peb[h*64 + tid];
    __syncthreads();

    int n0 = w*16 + r;
    float accS[8][4];
#pragma unroll
    for (int mt = 0; mt < 8; mt++)
#pragma unroll
        for (int j = 0; j < 4; j++) accS[mt][j] = 0.f;
#pragma unroll
    for (int ks = 0; ks < 4; ks++) {
        int d0 = ks*8 + qd;
        uint32_t av[4] = { uq[d0*68 + n0], uq[d0*68 + n0 + 8],
                           uq[(d0+4)*68 + n0], uq[(d0+4)*68 + n0 + 8] };
#pragma unroll
        for (int mt = 0; mt < 8; mt++) {
            uint32_t bv[2] = { uq[(32+d0)*68 + mt*8 + r], uq[(36+d0)*68 + mt*8 + r] };
            mma_m16n8k8(accS[mt], av, bv);
        }
    }
    // softmax (rows n0 and n0+8, distributed over the lane quad)
    const float SCALE = 0.17677669529663687f;
    float mx1 = -1e30f, mx2 = -1e30f;
#pragma unroll
    for (int mt = 0; mt < 8; mt++) {
        accS[mt][0] *= SCALE; accS[mt][1] *= SCALE; accS[mt][2] *= SCALE; accS[mt][3] *= SCALE;
        mx1 = fmaxf(mx1, fmaxf(accS[mt][0], accS[mt][1]));
        mx2 = fmaxf(mx2, fmaxf(accS[mt][2], accS[mt][3]));
    }
    mx1 = fmaxf(mx1, __shfl_xor_sync(~0u, mx1, 1)); mx1 = fmaxf(mx1, __shfl_xor_sync(~0u, mx1, 2));
    mx2 = fmaxf(mx2, __shfl_xor_sync(~0u, mx2, 1)); mx2 = fmaxf(mx2, __shfl_xor_sync(~0u, mx2, 2));
    float s1 = 0.f, s2 = 0.f;
#pragma unroll
    for (int mt = 0; mt < 8; mt++) {
        accS[mt][0] = __expf(accS[mt][0]-mx1); accS[mt][1] = __expf(accS[mt][1]-mx1);
        accS[mt][2] = __expf(accS[mt][2]-mx2); accS[mt][3] = __expf(accS[mt][3]-mx2);
        s1 += accS[mt][0] + accS[mt][1];
        s2 += accS[mt][2] + accS[mt][3];
    }
    s1 += __shfl_xor_sync(~0u, s1, 1); s1 += __shfl_xor_sync(~0u, s1, 2);
    s2 += __shfl_xor_sync(~0u, s2, 1); s2 += __shfl_xor_sync(~0u, s2, 2);
    float inv1 = 1.f/s1, inv2 = 1.f/s2;
#pragma unroll
    for (int mt = 0; mt < 8; mt++) {
        int m = mt*8 + 2*qd;
        uS[n0*68 + m]       = f2tf32(accS[mt][0]*inv1);
        uS[n0*68 + m+1]     = f2tf32(accS[mt][1]*inv1);
        uS[(n0+8)*68 + m]   = f2tf32(accS[mt][2]*inv2);
        uS[(n0+8)*68 + m+1] = f2tf32(accS[mt][3]*inv2);
    }
    __syncwarp();

    float accO[8][4];
#pragma unroll
    for (int nt = 0; nt < 8; nt++)
#pragma unroll
        for (int j = 0; j < 4; j++) accO[nt][j] = 0.f;
#pragma unroll
    for (int ks = 0; ks < 8; ks++) {
        int m0 = ks*8 + qd;
        uint32_t av[4] = { uS[n0*68 + m0], uS[(n0+8)*68 + m0],
                           uS[n0*68 + m0+4], uS[(n0+8)*68 + m0+4] };
#pragma unroll
        for (int nt = 0; nt < 8; nt++) {
            uint32_t bv[2] = { uq[(64+nt*8+r)*68 + m0], uq[(64+nt*8+r)*68 + m0+4] };
            mma_m16n8k8(accO[nt], av, bv);
        }
    }
    __syncthreads();           // all warps done reading uS; reuse as sO[dd][n]
#pragma unroll
    for (int nt = 0; nt < 8; nt++) {
        int dd = nt*8 + 2*qd;
        sSO[dd*68 + n0]       = accO[nt][0];
        sSO[(dd+1)*68 + n0]   = accO[nt][1];
        sSO[dd*68 + n0+8]     = accO[nt][2];
        sSO[(dd+1)*68 + n0+8] = accO[nt][3];
    }
    __syncthreads();
    // PE conv + bias + coalesced store: lane -> spatial n, loop over dd
    int n = (tid & 31) + ((w & 1) << 5);
    int p = n >> 3, qn = n & 7;
    int ddb = (w >> 1) * 32;
    float* ob = oall + COL8_BASE + (size_t)t*64 + n;
#pragma unroll 4
    for (int i = 0; i < 32; i++) {
        int dd = ddb + i;
        const float* wt = &swt[dd*10];
        float cv = sSO[dd*68 + n] + wt[9];
        const uint32_t* vr = &uq[(64+dd)*68];
#pragma unroll
        for (int u = 0; u < 3; u++) {
            int pp = p+u-1;
            if ((unsigned)pp < 8u)
#pragma unroll
                for (int v = 0; v < 3; v++) {
                    int qq = qn+v-1;
                    if ((unsigned)qq < 8u)
                        cv += wt[u*3+v] * __uint_as_float(vr[pp*8+qq]);
                }
        }
        ob[(size_t)(h*64+dd)*NCOL] = cv;
    }
}

// ---------------- stage 3b: attention K=4 (tensor cores) --------------------
// grid (2048), 128 thr; warp = head
__global__ __launch_bounds__(128) void attn4_mma(
    const float* __restrict__ q4, const float* __restrict__ pew,
    const float* __restrict__ peb, float* __restrict__ oall)
{
    extern __shared__ float sm4[];
    float* sqkv = sm4;                  // [512][20] tf32 bits
    float* sS   = sm4 + 512*20;         // [4][16][20]
    float* sO   = sS + 4*16*20;         // [256][20]
    float* swt  = sO + 256*20;          // [256][10]
    uint32_t* uq = (uint32_t*)sqkv;
    int t = blockIdx.x, tid = threadIdx.x;
    int lane = tid & 31, w = tid >> 5, r = lane >> 2, qd = lane & 3;

    const float4* src = (const float4*)(q4 + (size_t)t*512*16);
    for (int i4 = tid; i4 < 2048; i4 += 128) {
        int row = i4 >> 2, c4 = (i4 & 3) << 2;
        float4 v = src[i4];
        uint32_t* p = &uq[row*20 + c4];
        p[0]=f2tf32(v.x); p[1]=f2tf32(v.y); p[2]=f2tf32(v.z); p[3]=f2tf32(v.w);
    }
    for (int i = tid; i < 2304; i += 128) {
        int ch = i / 9, k = i - ch*9;
        swt[ch*10 + k] = pew[i];
    }
    for (int i = tid; i < 256; i += 128) swt[i*10+9] = peb[i];
    __syncthreads();

    int hb = w * 128;
    uint32_t* uSh = (uint32_t*)(sS + w*16*20);
    float accS[2][4];
#pragma unroll
    for (int mt = 0; mt < 2; mt++)
#pragma unroll
        for (int j = 0; j < 4; j++) accS[mt][j] = 0.f;
#pragma unroll
    for (int ks = 0; ks < 4; ks++) {
        int d0 = ks*8 + qd;
        uint32_t av[4] = { uq[(hb+d0)*20 + r], uq[(hb+d0)*20 + r + 8],
                           uq[(hb+d0+4)*20 + r], uq[(hb+d0+4)*20 + r + 8] };
#pragma unroll
        for (int mt = 0; mt < 2; mt++) {
            uint32_t bv[2] = { uq[(hb+32+d0)*20 + mt*8 + r], uq[(hb+36+d0)*20 + mt*8 + r] };
            mma_m16n8k8(accS[mt], av, bv);
        }
    }
    const float SCALE = 0.17677669529663687f;
    float mx1 = -1e30f, mx2 = -1e30f;
#pragma unroll
    for (int mt = 0; mt < 2; mt++) {
        accS[mt][0] *= SCALE; accS[mt][1] *= SCALE; accS[mt][2] *= SCALE; accS[mt][3] *= SCALE;
        mx1 = fmaxf(mx1, fmaxf(accS[mt][0], accS[mt][1]));
        mx2 = fmaxf(mx2, fmaxf(accS[mt][2], accS[mt][3]));
    }
    mx1 = fmaxf(mx1, __shfl_xor_sync(~0u, mx1, 1)); mx1 = fmaxf(mx1, __shfl_xor_sync(~0u, mx1, 2));
    mx2 = fmaxf(mx2, __shfl_xor_sync(~0u, mx2, 1)); mx2 = fmaxf(mx2, __shfl_xor_sync(~0u, mx2, 2));
    float s1 = 0.f, s2 = 0.f;
#pragma unroll
    for (int mt = 0; mt < 2; mt++) {
        accS[mt][0] = __expf(accS[mt][0]-mx1); accS[mt][1] = __expf(accS[mt][1]-mx1);
        accS[mt][2] = __expf(accS[mt][2]-mx2); accS[mt][3] = __expf(accS[mt][3]-mx2);
        s1 += accS[mt][0] + accS[mt][1];
        s2 += accS[mt][2] + accS[mt][3];
    }
    s1 += __shfl_xor_sync(~0u, s1, 1); s1 += __shfl_xor_sync(~0u, s1, 2);
    s2 += __shfl_xor_sync(~0u, s2, 1); s2 += __shfl_xor_sync(~0u, s2, 2);
    float inv1 = 1.f/s1, inv2 = 1.f/s2;
#pragma unroll
    for (int mt = 0; mt < 2; mt++) {
        int m = mt*8 + 2*qd;
        uSh[r*20 + m]       = f2tf32(accS[mt][0]*inv1);
        uSh[r*20 + m+1]     = f2tf32(accS[mt][1]*inv1);
        uSh[(r+8)*20 + m]   = f2tf32(accS[mt][2]*inv2);
        uSh[(r+8)*20 + m+1] = f2tf32(accS[mt][3]*inv2);
    }
    __syncwarp();

    float accO[8][4];
#pragma unroll
    for (int nt = 0; nt < 8; nt++)
#pragma unroll
        for (int j = 0; j < 4; j++) accO[nt][j] = 0.f;
#pragma unroll
    for (int ks = 0; ks < 2; ks++) {
        int m0 = ks*8 + qd;
        uint32_t av[4] = { uSh[r*20 + m0], uSh[(r+8)*20 + m0],
                           uSh[r*20 + m0+4], uSh[(r+8)*20 + m0+4] };
#pragma unroll
        for (int nt = 0; nt < 8; nt++) {
            uint32_t bv[2] = { uq[(hb+64+nt*8+r)*20 + m0], uq[(hb+64+nt*8+r)*20 + m0+4] };
            mma_m16n8k8(accO[nt], av, bv);
        }
    }
    __syncthreads();
#pragma unroll
    for (int nt = 0; nt < 8; nt++) {
        int c = w*64 + nt*8 + 2*qd;
        sO[c*20 + r]       = accO[nt][0];
        sO[(c+1)*20 + r]   = accO[nt][1];
        sO[c*20 + r+8]     = accO[nt][2];
        sO[(c+1)*20 + r+8] = accO[nt][3];
    }
    __syncthreads();
    // conv + store: lane -> n (16), 32 channels per thread
    int n = lane & 15, p = n >> 2, qn = n & 3;
    int cb = (w*2 + (lane >> 4)) * 32;
    float* ob = oall + (size_t)t*16 + n;
#pragma unroll 4
    for (int i = 0; i < 32; i++) {
        int c = cb + i;
        int hh = c >> 6, dd = c & 63;
        const float* wt = &swt[c*10];
        float cv = sO[c*20 + n] + wt[9];
        const uint32_t* vr = &uq[(hh*128 + 64 + dd)*20];
#pragma unroll
        for (int u = 0; u < 3; u++) {
            int pp = p+u-1;
            if ((unsigned)pp < 4u)
#pragma unroll
                for (int v = 0; v < 3; v++) {
                    int qq = qn+v-1;
                    if ((unsigned)qq < 4u)
                        cv += wt[u*3+v] * __uint_as_float(vr[pp*4+qq]);
                }
        }
        ob[(size_t)c*NCOL] = cv;
    }
}

// ---------------- stage 5: gather-fold + final average ----------------------
__global__ void combine_kernel(const float* __restrict__ x,
                               const float* __restrict__ a4,
                               const float* __restrict__ a8,
                               float* __restrict__ out)
{
    int idx = blockIdx.x*256 + threadIdx.x;
    if (idx >= N_*C_*H_*H_) return;
    int w = idx & 63;
    int h = (idx >> 6) & 63;
    int c = (idx >> 12) & 255;
    int n = idx >> 20;
    float xv = x[idx];
    {
        int p = h & 3, lh = h >> 2, q = w & 3, lw = w >> 2;
        xv += a4[(size_t)n*(256*16*256) + ((c*4+p)*4+q)*256 + lh*16 + lw];
    }
    float v8 = 0.f; int cnt = 0;
    int l1h = h >> 2, l1w = w >> 2;
#pragma unroll
    for (int dh = 0; dh < 2; dh++) {
        int lh = l1h - dh;
        if (lh < 0 || lh > 14) continue;
        int p = h - 4*lh;
#pragma unroll
        for (int dw = 0; dw < 2; dw++) {
            int lw = l1w - dw;
            if (lw < 0 || lw > 14) continue;
            int q = w - 4*lw;
            v8 += a8[(size_t)n*(256*64*225) + ((c*8+p)*8+q)*225 + lh*15 + lw];
            cnt++;
        }
    }
    out[idx] = (xv + v8 * (1.f/(float)cnt)) * (1.f/3.f);
}

// ---------------------------------------------------------------------------
extern "C" void kernel_launch(void* const* d_in, const int* in_sizes, int n_in,
                              void* d_out, int out_size)
{
    const float* x     = (const float*)d_in[0];
    const float* qkvw  = (const float*)d_in[1];
    const float* qkvb  = (const float*)d_in[2];
    const float* projw = (const float*)d_in[3];
    const float* projb = (const float*)d_in[4];
    const float* apew  = (const float*)d_in[5];
    const float* apeb  = (const float*)d_in[6];
    const float* dpew  = (const float*)d_in[7];
    const float* dpeb  = (const float*)d_in[8];
    float* out = (float*)d_out;

    float *yall,*oall,*q4,*q8,*a4,*a8;
    cudaGetSymbolAddress((void**)&yall, g_y);
    cudaGetSymbolAddress((void**)&oall, g_o);
    cudaGetSymbolAddress((void**)&q4,   g_q4);
    cudaGetSymbolAddress((void**)&q8,   g_q8);
    cudaGetSymbolAddress((void**)&a4,   g_a4);
    cudaGetSymbolAddress((void**)&a8,   g_a8);

    int attn8_smem = (128*68 + 64*68 + 64*10) * sizeof(float);
    int attn4_smem = (512*20 + 4*16*20 + 256*20 + 256*10) * sizeof(float);
    cudaFuncSetAttribute(attn8_mma, cudaFuncAttributeMaxDynamicSharedMemorySize, attn8_smem);
    cudaFuncSetAttribute(attn4_mma, cudaFuncAttributeMaxDynamicSharedMemorySize, attn4_smem);

    pool4_kernel<<<dim3(16, 8, 16), 256>>>(x, dpew, dpeb, yall);
    pool8_kernel<<<dim3(15, 8, 64), 256>>>(x, dpew, dpeb, yall);

    mma_gemm<<<dim3(4, NCOL/128), 256>>>(qkvw, qkvb, yall, q4, q8, 512);

    attn4_mma<<<2048, 128, attn4_smem>>>(q4, apew, apeb, oall);
    attn8_mma<<<dim3(1800, 4), 128, attn8_smem>>>(q8, apew, apeb, oall);

    mma_gemm<<<dim3(2, NCOL/128), 256>>>(projw, projb, oall, a4, a8, 256);

    combine_kernel<<<(N_*C_*H_*H_ + 255)/256, 256>>>(x, a4, a8, out);
}

// round 12
// speedup vs baseline: 5.9466x; 1.7842x over previous
#include <cuda_runtime.h>
#include <cuda_fp16.h>
#include <cstdint>

#define N_ 8
#define C_ 256
#define H_ 64
#define NCOL 147968            // 2048*16 + 1800*64
#define COL8_BASE 32768

// ---------------- scratch ---------------------------------------------------
__device__ float g_y [(size_t)256*NCOL];        // y_all [c][col]
__device__ float g_o [(size_t)256*NCOL];        // attn out [c][col]
__device__ float g_q4[(size_t)2048*512*16];     // qkv K=4 [t][512][16]
__device__ float g_q8[(size_t)1800*512*64];     // qkv K=8 [t][512][64]
__device__ float g_a4[(size_t)2048*256*16];
__device__ float g_a8[(size_t)1800*256*64];

// ---------------- helpers ----------------------------------------------------
__device__ __forceinline__ uint32_t f2tf32(float f) {
    uint32_t r;
    asm("cvt.rna.tf32.f32 %0, %1;" : "=r"(r) : "f"(f));
    return r;
}
__device__ __forceinline__ void mma_m16n8k8(float* c, const uint32_t* a, const uint32_t* b) {
    asm volatile("mma.sync.aligned.m16n8k8.row.col.f32.tf32.tf32.f32 "
        "{%0,%1,%2,%3}, {%4,%5,%6,%7}, {%8,%9}, {%0,%1,%2,%3};"
        : "+f"(c[0]), "+f"(c[1]), "+f"(c[2]), "+f"(c[3])
        : "r"(a[0]), "r"(a[1]), "r"(a[2]), "r"(a[3]), "r"(b[0]), "r"(b[1]));
}
__device__ __forceinline__ void mma_m16n8k16h(float* c, const uint32_t* a, const uint32_t* b) {
    asm volatile("mma.sync.aligned.m16n8k16.row.col.f32.f16.f16.f32 "
        "{%0,%1,%2,%3}, {%4,%5,%6,%7}, {%8,%9}, {%0,%1,%2,%3};"
        : "+f"(c[0]), "+f"(c[1]), "+f"(c[2]), "+f"(c[3])
        : "r"(a[0]), "r"(a[1]), "r"(a[2]), "r"(a[3]), "r"(b[0]), "r"(b[1]));
}
__device__ __forceinline__ uint32_t h2pack(float lo, float hi) {
    __half2 h = __floats2half2_rn(lo, hi);
    return *(uint32_t*)&h;
}

// ---------------- stage 1a: pool+dwconv K=4 -> y_all[c][col] ----------------
__global__ __launch_bounds__(256) void pool4_kernel(
    const float* __restrict__ x, const float* __restrict__ dpw,
    const float* __restrict__ dpb, float* __restrict__ yall)
{
    __shared__ float sx[16*448];      // [c][7][64]
    __shared__ float sp[16*272];      // [c][b(16) stride 17][s(16)]
    int a = blockIdx.x, n = blockIdx.y, cbase = blockIdx.z * 16;
    int tid = threadIdx.x;
    for (int i4 = tid; i4 < 1792; i4 += 256) {
        int c = i4 / 112, rem = i4 - c*112;
        int hh = rem >> 4, w4 = (rem & 15) << 2;
        int gh = min(max(a*4 - 1 + hh, 0), 63);
        float4 v = *(const float4*)(x + (((size_t)(n*C_ + cbase + c)*64 + gh) << 6) + w4);
        *(float4*)(sx + c*448 + hh*64 + w4) = v;
    }
    __syncthreads();
    {
        int c = tid >> 4, b = tid & 15;
        const float* sxc = sx + c*448;
#pragma unroll
        for (int s = 0; s < 16; s++) {
            int p = s >> 2, q = s & 3;
            int rl = (p*6) >> 2;
            int w0 = b*4 + ((q*6) >> 2) - 1;
            int wa = min(max(w0, 0), 63), wb = min(max(w0+1, 0), 63);
            float acc = 0.25f * (sxc[rl*64 + wa] + sxc[rl*64 + wb] +
                                 sxc[(rl+1)*64 + wa] + sxc[(rl+1)*64 + wb]);
            sp[c*272 + b*17 + s] = acc;
        }
    }
    __syncthreads();
    {
        int c = tid >> 4, b = tid & 15;
        const float* wc = dpw + (cbase + c)*9;
        float bv = dpb[cbase + c];
        const float* spc = sp + c*272 + b*17;
        float outv[16];
#pragma unroll
        for (int s = 0; s < 16; s++) {
            int p = s >> 2, q = s & 3;
            float r = spc[s] + bv;
#pragma unroll
            for (int u = 0; u < 3; u++)
#pragma unroll
                for (int v = 0; v < 3; v++) {
                    int pp = p+u-1, qq = q+v-1;
                    if (pp >= 0 && pp < 4 && qq >= 0 && qq < 4)
                        r += wc[u*3+v] * spc[pp*4+qq];
                }
            outv[s] = r;
        }
        float* dst = yall + (size_t)(cbase + c)*NCOL + (((n<<8) + (a<<4) + b) << 4);
#pragma unroll
        for (int j = 0; j < 4; j++)
            *(float4*)(dst + j*4) = make_float4(outv[j*4], outv[j*4+1], outv[j*4+2], outv[j*4+3]);
    }
}

// ---------------- stage 1b: pool+dwconv K=8 ---------------------------------
__global__ __launch_bounds__(256) void pool8_kernel(
    const float* __restrict__ x, const float* __restrict__ dpw,
    const float* __restrict__ dpb, float* __restrict__ yall)
{
    __shared__ float sx[4*704];       // [c][11][64]
    __shared__ float sp[4*960];       // [c][b(15)][s(64)]
    int a = blockIdx.x, n = blockIdx.y, cbase = blockIdx.z * 4;
    int tid = threadIdx.x;
    for (int i4 = tid; i4 < 704; i4 += 256) {
        int c = i4 / 176, rem = i4 - c*176;
        int hh = rem >> 4, w4 = (rem & 15) << 2;
        int gh = min(max(a*4 - 1 + hh, 0), 63);
        float4 v = *(const float4*)(x + (((size_t)(n*C_ + cbase + c)*64 + gh) << 6) + w4);
        *(float4*)(sx + c*704 + hh*64 + w4) = v;
    }
    __syncthreads();
    {
        int c = tid >> 6, s = tid & 63;
        int p = s >> 3, q = s & 7;
        int rl = (p*10) >> 3;
        int cq = (q*10) >> 3;
        const float* sxc = sx + c*704;
#pragma unroll
        for (int b = 0; b < 15; b++) {
            int w0 = b*4 + cq - 1;
            int wa = min(max(w0, 0), 63), wb = min(max(w0+1, 0), 63);
            sp[c*960 + b*64 + s] = 0.25f * (sxc[rl*64 + wa] + sxc[rl*64 + wb] +
                                            sxc[(rl+1)*64 + wa] + sxc[(rl+1)*64 + wb]);
        }
    }
    __syncthreads();
    {
        int c = tid >> 6, s = tid & 63;
        int p = s >> 3, q = s & 7;
        const float* wc = dpw + (cbase + c)*9;
        float bv = dpb[cbase + c];
        float* dst = yall + (size_t)(cbase + c)*NCOL + COL8_BASE + ((size_t)(n*225 + a*15) << 6) + s;
#pragma unroll
        for (int b = 0; b < 15; b++) {
            const float* spc = sp + c*960 + b*64;
            float r = spc[s] + bv;
#pragma unroll
            for (int u = 0; u < 3; u++)
#pragma unroll
                for (int v = 0; v < 3; v++) {
                    int pp = p+u-1, qq = q+v-1;
                    if (pp >= 0 && pp < 8 && qq >= 0 && qq < 8)
                        r += wc[u*3+v] * spc[pp*8+qq];
                }
            dst[b << 6] = r;
        }
    }
}

// ---------------- fp16 mma.sync GEMM ----------------------------------------
// D[M x NCOL] = W[M,256] @ Y (+bias), Y stored [c][col]. CTA 128x128.
// As[row][kpair] uint32=half2, stride 12 (conflict-free, 16B-aligned stores)
// Bs[kpair][col] stride 136 (conflict-free)
#define AST 12
#define BST 136
__global__ __launch_bounds__(256) void mma_gemm(
    const float* __restrict__ W, const float* __restrict__ bias,
    const float* __restrict__ Bm,
    float* __restrict__ out4, float* __restrict__ out8, int OD)
{
    __shared__ uint32_t As[2][128*AST];
    __shared__ uint32_t Bs[2][8*BST];
    int tid = threadIdx.x, lane = tid & 31, wid = tid >> 5;
    int warpM = wid & 1, warpN = wid >> 1;
    int mrow0 = blockIdx.x * 128, col0 = blockIdx.y * 128;
    const float* Ap = W + (size_t)mrow0 * 256;

    int r     = tid >> 1;            // A loader: row 0..127
    int halfo = (tid & 1) * 8;       // k offset 0 or 8
    int bj    = tid >> 5;            // B loader: kpair 0..7
    int bcol  = lane * 4;            // 4 cols

    float acc[4][4][4];
#pragma unroll
    for (int mt = 0; mt < 4; mt++)
#pragma unroll
        for (int nt = 0; nt < 4; nt++)
#pragma unroll
            for (int i = 0; i < 4; i++) acc[mt][nt][i] = 0.f;

    // prologue: chunk 0 -> buf 0
    {
        float4 a0 = *(const float4*)(Ap + (size_t)r*256 + halfo);
        float4 a1 = *(const float4*)(Ap + (size_t)r*256 + halfo + 4);
        uint4 av;
        av.x = h2pack(a0.x, a0.y); av.y = h2pack(a0.z, a0.w);
        av.z = h2pack(a1.x, a1.y); av.w = h2pack(a1.z, a1.w);
        *(uint4*)&As[0][r*AST + (halfo >> 1)] = av;
        float4 b0 = *(const float4*)(Bm + (size_t)(2*bj  )*NCOL + col0 + bcol);
        float4 b1 = *(const float4*)(Bm + (size_t)(2*bj+1)*NCOL + col0 + bcol);
        uint4 bv;
        bv.x = h2pack(b0.x, b1.x); bv.y = h2pack(b0.y, b1.y);
        bv.z = h2pack(b0.z, b1.z); bv.w = h2pack(b0.w, b1.w);
        *(uint4*)&Bs[0][bj*BST + bcol] = bv;
    }
    __syncthreads();

    int rowA = warpM*64 + (lane >> 2);
    int rowB = warpN*32 + (lane >> 2);
    int kq   = lane & 3;

    for (int kc = 0; kc < 16; kc++) {
        int buf = kc & 1;
        float4 a0, a1, b0, b1;
        if (kc < 15) {
            const float* ap = Ap + (size_t)r*256 + (kc+1)*16 + halfo;
            a0 = *(const float4*)(ap);     a1 = *(const float4*)(ap + 4);
            b0 = *(const float4*)(Bm + (size_t)((kc+1)*16 + 2*bj  )*NCOL + col0 + bcol);
            b1 = *(const float4*)(Bm + (size_t)((kc+1)*16 + 2*bj+1)*NCOL + col0 + bcol);
        }
        {
            uint32_t af[4][4], bf[4][2];
#pragma unroll
            for (int mt = 0; mt < 4; mt++) {
                int row = rowA + mt*16;
                af[mt][0] = As[buf][row*AST + kq];
                af[mt][1] = As[buf][(row+8)*AST + kq];
                af[mt][2] = As[buf][row*AST + kq + 4];
                af[mt][3] = As[buf][(row+8)*AST + kq + 4];
            }
#pragma unroll
            for (int nt = 0; nt < 4; nt++) {
                int coln = rowB + nt*8;
                bf[nt][0] = Bs[buf][kq*BST + coln];
                bf[nt][1] = Bs[buf][(kq+4)*BST + coln];
            }
#pragma unroll
            for (int mt = 0; mt < 4; mt++)
#pragma unroll
                for (int nt = 0; nt < 4; nt++)
                    mma_m16n8k16h(acc[mt][nt], af[mt], bf[nt]);
        }
        if (kc < 15) {
            uint4 av;
            av.x = h2pack(a0.x, a0.y); av.y = h2pack(a0.z, a0.w);
            av.z = h2pack(a1.x, a1.y); av.w = h2pack(a1.z, a1.w);
            *(uint4*)&As[buf^1][r*AST + (halfo >> 1)] = av;
            uint4 bv;
            bv.x = h2pack(b0.x, b1.x); bv.y = h2pack(b0.y, b1.y);
            bv.z = h2pack(b0.z, b1.z); bv.w = h2pack(b0.w, b1.w);
            *(uint4*)&Bs[buf^1][bj*BST + bcol] = bv;
        }
        __syncthreads();
    }

#pragma unroll
    for (int mt = 0; mt < 4; mt++) {
        int m0 = mrow0 + warpM*64 + mt*16 + (lane >> 2);
        float bv0 = bias[m0], bv1 = bias[m0 + 8];
#pragma unroll
        for (int nt = 0; nt < 4; nt++) {
            int coln = col0 + warpN*32 + nt*8 + (lane & 3)*2;
            float2 v0 = make_float2(acc[mt][nt][0] + bv0, acc[mt][nt][1] + bv0);
            float2 v1 = make_float2(acc[mt][nt][2] + bv1, acc[mt][nt][3] + bv1);
            if (coln < COL8_BASE) {
                int t0 = coln >> 4, s = coln & 15;
                *(float2*)(out4 + ((size_t)t0*OD + m0    )*16 + s) = v0;
                *(float2*)(out4 + ((size_t)t0*OD + m0 + 8)*16 + s) = v1;
            } else {
                int t0 = (coln - COL8_BASE) >> 6, s = coln & 63;
                *(float2*)(out8 + ((size_t)t0*OD + m0    )*64 + s) = v0;
                *(float2*)(out8 + ((size_t)t0*OD + m0 + 8)*64 + s) = v1;
            }
        }
    }
}

// ---------------- stage 3a: attention K=8 (tensor cores) --------------------
__global__ __launch_bounds__(128) void attn8_mma(
    const float* __restrict__ q8, const float* __restrict__ pew,
    const float* __restrict__ peb, float* __restrict__ oall)
{
    extern __shared__ float sm8[];
    float* sqkv = sm8;                 // [128][68] (tf32 bits)
    float* sSO  = sm8 + 128*68;        // [64][68]
    float* swt  = sSO + 64*68;         // [64][10]
    uint32_t* uq = (uint32_t*)sqkv;
    uint32_t* uS = (uint32_t*)sSO;
    int t = blockIdx.x, h = blockIdx.y, tid = threadIdx.x;
    int lane = tid & 31, w = tid >> 5, r = lane >> 2, qd = lane & 3;

    const float4* src = (const float4*)(q8 + ((size_t)t*512 + h*128)*64);
    for (int i4 = tid; i4 < 2048; i4 += 128) {
        int row = i4 >> 4, c4 = (i4 & 15) << 2;
        float4 v = src[i4];
        uint32_t* p = &uq[row*68 + c4];
        p[0]=f2tf32(v.x); p[1]=f2tf32(v.y); p[2]=f2tf32(v.z); p[3]=f2tf32(v.w);
    }
    for (int i = tid; i < 576; i += 128) {
        int ch = i / 9, k = i - ch*9;
        swt[ch*10 + k] = pew[(h*64+ch)*9 + k];
    }
    if (tid < 64) swt[tid*10+9] = peb[h*64 + tid];
    __syncthreads();

    int n0 = w*16 + r;
    float accS[8][4];
#pragma unroll
    for (int mt = 0; mt < 8; mt++)
#pragma unroll
        for (int j = 0; j < 4; j++) accS[mt][j] = 0.f;
#pragma unroll
    for (int ks = 0; ks < 4; ks++) {
        int d0 = ks*8 + qd;
        uint32_t av[4] = { uq[d0*68 + n0], uq[d0*68 + n0 + 8],
                           uq[(d0+4)*68 + n0], uq[(d0+4)*68 + n0 + 8] };
#pragma unroll
        for (int mt = 0; mt < 8; mt++) {
            uint32_t bv[2] = { uq[(32+d0)*68 + mt*8 + r], uq[(36+d0)*68 + mt*8 + r] };
            mma_m16n8k8(accS[mt], av, bv);
        }
    }
    const float SCALE = 0.17677669529663687f;
    float mx1 = -1e30f, mx2 = -1e30f;
#pragma unroll
    for (int mt = 0; mt < 8; mt++) {
        accS[mt][0] *= SCALE; accS[mt][1] *= SCALE; accS[mt][2] *= SCALE; accS[mt][3] *= SCALE;
        mx1 = fmaxf(mx1, fmaxf(accS[mt][0], accS[mt][1]));
        mx2 = fmaxf(mx2, fmaxf(accS[mt][2], accS[mt][3]));
    }
    mx1 = fmaxf(mx1, __shfl_xor_sync(~0u, mx1, 1)); mx1 = fmaxf(mx1, __shfl_xor_sync(~0u, mx1, 2));
    mx2 = fmaxf(mx2, __shfl_xor_sync(~0u, mx2, 1)); mx2 = fmaxf(mx2, __shfl_xor_sync(~0u, mx2, 2));
    float s1 = 0.f, s2 = 0.f;
#pragma unroll
    for (int mt = 0; mt < 8; mt++) {
        accS[mt][0] = __expf(accS[mt][0]-mx1); accS[mt][1] = __expf(accS[mt][1]-mx1);
        accS[mt][2] = __expf(accS[mt][2]-mx2); accS[mt][3] = __expf(accS[mt][3]-mx2);
        s1 += accS[mt][0] + accS[mt][1];
        s2 += accS[mt][2] + accS[mt][3];
    }
    s1 += __shfl_xor_sync(~0u, s1, 1); s1 += __shfl_xor_sync(~0u, s1, 2);
    s2 += __shfl_xor_sync(~0u, s2, 1); s2 += __shfl_xor_sync(~0u, s2, 2);
    float inv1 = 1.f/s1, inv2 = 1.f/s2;
#pragma unroll
    for (int mt = 0; mt < 8; mt++) {
        int m = mt*8 + 2*qd;
        uS[n0*68 + m]       = f2tf32(accS[mt][0]*inv1);
        uS[n0*68 + m+1]     = f2tf32(accS[mt][1]*inv1);
        uS[(n0+8)*68 + m]   = f2tf32(accS[mt][2]*inv2);
        uS[(n0+8)*68 + m+1] = f2tf32(accS[mt][3]*inv2);
    }
    __syncwarp();

    float accO[8][4];
#pragma unroll
    for (int nt = 0; nt < 8; nt++)
#pragma unroll
        for (int j = 0; j < 4; j++) accO[nt][j] = 0.f;
#pragma unroll
    for (int ks = 0; ks < 8; ks++) {
        int m0 = ks*8 + qd;
        uint32_t av[4] = { uS[n0*68 + m0], uS[(n0+8)*68 + m0],
                           uS[n0*68 + m0+4], uS[(n0+8)*68 + m0+4] };
#pragma unroll
        for (int nt = 0; nt < 8; nt++) {
            uint32_t bv[2] = { uq[(64+nt*8+r)*68 + m0], uq[(64+nt*8+r)*68 + m0+4] };
            mma_m16n8k8(accO[nt], av, bv);
        }
    }
    __syncthreads();
#pragma unroll
    for (int nt = 0; nt < 8; nt++) {
        int dd = nt*8 + 2*qd;
        sSO[dd*68 + n0]       = accO[nt][0];
        sSO[(dd+1)*68 + n0]   = accO[nt][1];
        sSO[dd*68 + n0+8]     = accO[nt][2];
        sSO[(dd+1)*68 + n0+8] = accO[nt][3];
    }
    __syncthreads();
    int n = (tid & 31) + ((w & 1) << 5);
    int p = n >> 3, qn = n & 7;
    int ddb = (w >> 1) * 32;
    float* ob = oall + COL8_BASE + (size_t)t*64 + n;
#pragma unroll 4
    for (int i = 0; i < 32; i++) {
        int dd = ddb + i;
        const float* wt = &swt[dd*10];
        float cv = sSO[dd*68 + n] + wt[9];
        const uint32_t* vr = &uq[(64+dd)*68];
#pragma unroll
        for (int u = 0; u < 3; u++) {
            int pp = p+u-1;
            if ((unsigned)pp < 8u)
#pragma unroll
                for (int v = 0; v < 3; v++) {
                    int qq = qn+v-1;
                    if ((unsigned)qq < 8u)
                        cv += wt[u*3+v] * __uint_as_float(vr[pp*8+qq]);
                }
        }
        ob[(size_t)(h*64+dd)*NCOL] = cv;
    }
}

// ---------------- stage 3b: attention K=4 (scalar) --------------------------
// grid (2048, 4), block 128. Output transposed to o_all[c][col].
__global__ __launch_bounds__(128) void attn4_scalar(
    const float* __restrict__ qkv, const float* __restrict__ pew,
    const float* __restrict__ peb, float* __restrict__ oall)
{
    __shared__ float sqkv[128*17];
    __shared__ float satt[16*17];
    int t = blockIdx.x, h = blockIdx.y, tid = threadIdx.x;
    const float4* src = (const float4*)(qkv + ((size_t)t*512 + h*128)*16);
    for (int i4 = tid; i4 < 512; i4 += 128) {
        int row = i4 >> 2, c4 = (i4 & 3) << 2;
        float4 v = src[i4];
        float* p = &sqkv[row*17 + c4];
        p[0]=v.x; p[1]=v.y; p[2]=v.z; p[3]=v.w;
    }
    __syncthreads();
    const float scale = 0.17677669529663687f;
    for (int idx = tid; idx < 256; idx += 128) {
        int m = idx & 15, n = idx >> 4;
        float d = 0.f;
#pragma unroll
        for (int dd = 0; dd < 32; dd++)
            d += sqkv[dd*17 + n] * sqkv[(32+dd)*17 + m];
        satt[n*17 + m] = d * scale;
    }
    __syncthreads();
    if (tid < 16) {
        float* row = &satt[tid*17];
        float mx = -1e30f;
#pragma unroll
        for (int m = 0; m < 16; m++) mx = fmaxf(mx, row[m]);
        float smv = 0.f;
#pragma unroll
        for (int m = 0; m < 16; m++) { float e = __expf(row[m]-mx); row[m] = e; smv += e; }
        float inv = 1.f/smv;
#pragma unroll
        for (int m = 0; m < 16; m++) row[m] *= inv;
    }
    __syncthreads();
    for (int idx = tid; idx < 1024; idx += 128) {
        int n = idx & 15, d = idx >> 4;
        const float* vrow = &sqkv[(64+d)*17];
        const float* arow = &satt[n*17];
        float acc = 0.f;
#pragma unroll
        for (int m = 0; m < 16; m++) acc += vrow[m]*arow[m];
        int c = h*64 + d;
        int p = n >> 2, q = n & 3;
        float r = acc + peb[c];
        const float* wc = pew + c*9;
#pragma unroll
        for (int u = 0; u < 3; u++) {
            int pp = p+u-1;
            if ((unsigned)pp < 4u)
#pragma unroll
                for (int v = 0; v < 3; v++) {
                    int qq = q+v-1;
                    if ((unsigned)qq < 4u)
                        r += wc[u*3+v] * vrow[pp*4+qq];
                }
        }
        oall[(size_t)c*NCOL + t*16 + n] = r;
    }
}

// ---------------- stage 5: gather-fold + final average ----------------------
__global__ void combine_kernel(const float* __restrict__ x,
                               const float* __restrict__ a4,
                               const float* __restrict__ a8,
                               float* __restrict__ out)
{
    int idx = blockIdx.x*256 + threadIdx.x;
    if (idx >= N_*C_*H_*H_) return;
    int w = idx & 63;
    int h = (idx >> 6) & 63;
    int c = (idx >> 12) & 255;
    int n = idx >> 20;
    float xv = x[idx];
    {
        int p = h & 3, lh = h >> 2, q = w & 3, lw = w >> 2;
        xv += a4[(size_t)n*(256*16*256) + ((c*4+p)*4+q)*256 + lh*16 + lw];
    }
    float v8 = 0.f; int cnt = 0;
    int l1h = h >> 2, l1w = w >> 2;
#pragma unroll
    for (int dh = 0; dh < 2; dh++) {
        int lh = l1h - dh;
        if (lh < 0 || lh > 14) continue;
        int p = h - 4*lh;
#pragma unroll
        for (int dw = 0; dw < 2; dw++) {
            int lw = l1w - dw;
            if (lw < 0 || lw > 14) continue;
            int q = w - 4*lw;
            v8 += a8[(size_t)n*(256*64*225) + ((c*8+p)*8+q)*225 + lh*15 + lw];
            cnt++;
        }
    }
    out[idx] = (xv + v8 * (1.f/(float)cnt)) * (1.f/3.f);
}

// ---------------------------------------------------------------------------
extern "C" void kernel_launch(void* const* d_in, const int* in_sizes, int n_in,
                              void* d_out, int out_size)
{
    const float* x     = (const float*)d_in[0];
    const float* qkvw  = (const float*)d_in[1];
    const float* qkvb  = (const float*)d_in[2];
    const float* projw = (const float*)d_in[3];
    const float* projb = (const float*)d_in[4];
    const float* apew  = (const float*)d_in[5];
    const float* apeb  = (const float*)d_in[6];
    const float* dpew  = (const float*)d_in[7];
    const float* dpeb  = (const float*)d_in[8];
    float* out = (float*)d_out;

    float *yall,*oall,*q4,*q8,*a4,*a8;
    cudaGetSymbolAddress((void**)&yall, g_y);
    cudaGetSymbolAddress((void**)&oall, g_o);
    cudaGetSymbolAddress((void**)&q4,   g_q4);
    cudaGetSymbolAddress((void**)&q8,   g_q8);
    cudaGetSymbolAddress((void**)&a4,   g_a4);
    cudaGetSymbolAddress((void**)&a8,   g_a8);

    int attn8_smem = (128*68 + 64*68 + 64*10) * sizeof(float);
    cudaFuncSetAttribute(attn8_mma, cudaFuncAttributeMaxDynamicSharedMemorySize, attn8_smem);

    pool4_kernel<<<dim3(16, 8, 16), 256>>>(x, dpew, dpeb, yall);
    pool8_kernel<<<dim3(15, 8, 64), 256>>>(x, dpew, dpeb, yall);

    mma_gemm<<<dim3(4, NCOL/128), 256>>>(qkvw, qkvb, yall, q4, q8, 512);

    attn4_scalar<<<dim3(2048, 4), 128>>>(q4, apew, apeb, oall);
    attn8_mma<<<dim3(1800, 4), 128, attn8_smem>>>(q8, apew, apeb, oall);

    mma_gemm<<<dim3(2, NCOL/128), 256>>>(projw, projb, oall, a4, a8, 256);

    combine_kernel<<<(N_*C_*H_*H_ + 255)/256, 256>>>(x, a4, a8, out);
}

// round 16
// speedup vs baseline: 6.4282x; 1.0810x over previous
#include <cuda_runtime.h>
#include <cuda_fp16.h>
#include <cstdint>

#define N_ 8
#define C_ 256
#define H_ 64
#define NCOL 147968            // 2048*16 + 1800*64
#define COL8_BASE 32768

// ---------------- scratch (uint4-typed for 16B alignment; cast to __half*) --
__device__ uint4 g_yh [(size_t)256*NCOL/8];        // y_all [c][col] half
__device__ uint4 g_oh [(size_t)256*NCOL/8];        // attn out [c][col] half
__device__ uint4 g_q4h[(size_t)2048*512*16/8];     // qkv K=4 [t][512][16] half
__device__ uint4 g_q8h[(size_t)1800*512*64/8];     // qkv K=8 [t][512][64] half
__device__ float g_a4 [(size_t)2048*256*16];
__device__ float g_a8 [(size_t)1800*256*64];

// ---------------- helpers ----------------------------------------------------
__device__ __forceinline__ uint32_t f2tf32(float f) {
    uint32_t r;
    asm("cvt.rna.tf32.f32 %0, %1;" : "=r"(r) : "f"(f));
    return r;
}
__device__ __forceinline__ void mma_m16n8k8(float* c, const uint32_t* a, const uint32_t* b) {
    asm volatile("mma.sync.aligned.m16n8k8.row.col.f32.tf32.tf32.f32 "
        "{%0,%1,%2,%3}, {%4,%5,%6,%7}, {%8,%9}, {%0,%1,%2,%3};"
        : "+f"(c[0]), "+f"(c[1]), "+f"(c[2]), "+f"(c[3])
        : "r"(a[0]), "r"(a[1]), "r"(a[2]), "r"(a[3]), "r"(b[0]), "r"(b[1]));
}
__device__ __forceinline__ void mma_m16n8k16h(float* c, const uint32_t* a, const uint32_t* b) {
    asm volatile("mma.sync.aligned.m16n8k16.row.col.f32.f16.f16.f32 "
        "{%0,%1,%2,%3}, {%4,%5,%6,%7}, {%8,%9}, {%0,%1,%2,%3};"
        : "+f"(c[0]), "+f"(c[1]), "+f"(c[2]), "+f"(c[3])
        : "r"(a[0]), "r"(a[1]), "r"(a[2]), "r"(a[3]), "r"(b[0]), "r"(b[1]));
}
__device__ __forceinline__ uint32_t h2pack(float lo, float hi) {
    __half2 h = __floats2half2_rn(lo, hi);
    return *(uint32_t*)&h;
}
__device__ __forceinline__ uint32_t h2u(__half2 h) { return *(uint32_t*)&h; }

// ---------------- stage 1a: pool+dwconv K=4 -> y_all[c][col] (half) ---------
__global__ __launch_bounds__(256) void pool4_kernel(
    const float* __restrict__ x, const float* __restrict__ dpw,
    const float* __restrict__ dpb, __half* __restrict__ yall)
{
    __shared__ float sx[16*448];      // [c][7][64]
    __shared__ float sp[16*272];      // [c][b(16) stride 17][s(16)]
    int a = blockIdx.x, n = blockIdx.y, cbase = blockIdx.z * 16;
    int tid = threadIdx.x;
    for (int i4 = tid; i4 < 1792; i4 += 256) {
        int c = i4 / 112, rem = i4 - c*112;
        int hh = rem >> 4, w4 = (rem & 15) << 2;
        int gh = min(max(a*4 - 1 + hh, 0), 63);
        float4 v = *(const float4*)(x + (((size_t)(n*C_ + cbase + c)*64 + gh) << 6) + w4);
        *(float4*)(sx + c*448 + hh*64 + w4) = v;
    }
    __syncthreads();
    {
        int c = tid >> 4, b = tid & 15;
        const float* sxc = sx + c*448;
#pragma unroll
        for (int s = 0; s < 16; s++) {
            int p = s >> 2, q = s & 3;
            int rl = (p*6) >> 2;
            int w0 = b*4 + ((q*6) >> 2) - 1;
            int wa = min(max(w0, 0), 63), wb = min(max(w0+1, 0), 63);
            float acc = 0.25f * (sxc[rl*64 + wa] + sxc[rl*64 + wb] +
                                 sxc[(rl+1)*64 + wa] + sxc[(rl+1)*64 + wb]);
            sp[c*272 + b*17 + s] = acc;
        }
    }
    __syncthreads();
    {
        int c = tid >> 4, b = tid & 15;
        const float* wc = dpw + (cbase + c)*9;
        float bv = dpb[cbase + c];
        const float* spc = sp + c*272 + b*17;
        float outv[16];
#pragma unroll
        for (int s = 0; s < 16; s++) {
            int p = s >> 2, q = s & 3;
            float r = spc[s] + bv;
#pragma unroll
            for (int u = 0; u < 3; u++)
#pragma unroll
                for (int v = 0; v < 3; v++) {
                    int pp = p+u-1, qq = q+v-1;
                    if (pp >= 0 && pp < 4 && qq >= 0 && qq < 4)
                        r += wc[u*3+v] * spc[pp*4+qq];
                }
            outv[s] = r;
        }
        __half* dst = yall + (size_t)(cbase + c)*NCOL + (((n<<8) + (a<<4) + b) << 4);
#pragma unroll
        for (int j = 0; j < 4; j++) {
            uint2 u;
            u.x = h2pack(outv[j*4+0], outv[j*4+1]);
            u.y = h2pack(outv[j*4+2], outv[j*4+3]);
            *(uint2*)(dst + j*4) = u;
        }
    }
}

// ---------------- stage 1b: pool+dwconv K=8 (half out) ----------------------
__global__ __launch_bounds__(256) void pool8_kernel(
    const float* __restrict__ x, const float* __restrict__ dpw,
    const float* __restrict__ dpb, __half* __restrict__ yall)
{
    __shared__ float sx[4*704];       // [c][11][64]
    __shared__ float sp[4*960];       // [c][b(15)][s(64)]
    int a = blockIdx.x, n = blockIdx.y, cbase = blockIdx.z * 4;
    int tid = threadIdx.x;
    for (int i4 = tid; i4 < 704; i4 += 256) {
        int c = i4 / 176, rem = i4 - c*176;
        int hh = rem >> 4, w4 = (rem & 15) << 2;
        int gh = min(max(a*4 - 1 + hh, 0), 63);
        float4 v = *(const float4*)(x + (((size_t)(n*C_ + cbase + c)*64 + gh) << 6) + w4);
        *(float4*)(sx + c*704 + hh*64 + w4) = v;
    }
    __syncthreads();
    {
        int c = tid >> 6, s = tid & 63;
        int p = s >> 3, q = s & 7;
        int rl = (p*10) >> 3;
        int cq = (q*10) >> 3;
        const float* sxc = sx + c*704;
#pragma unroll
        for (int b = 0; b < 15; b++) {
            int w0 = b*4 + cq - 1;
            int wa = min(max(w0, 0), 63), wb = min(max(w0+1, 0), 63);
            sp[c*960 + b*64 + s] = 0.25f * (sxc[rl*64 + wa] + sxc[rl*64 + wb] +
                                            sxc[(rl+1)*64 + wa] + sxc[(rl+1)*64 + wb]);
        }
    }
    __syncthreads();
    {
        int c = tid >> 6, s = tid & 63;
        int p = s >> 3, q = s & 7;
        const float* wc = dpw + (cbase + c)*9;
        float bv = dpb[cbase + c];
        __half* dst = yall + (size_t)(cbase + c)*NCOL + COL8_BASE + ((size_t)(n*225 + a*15) << 6) + s;
#pragma unroll
        for (int b = 0; b < 15; b++) {
            const float* spc = sp + c*960 + b*64;
            float r = spc[s] + bv;
#pragma unroll
            for (int u = 0; u < 3; u++)
#pragma unroll
                for (int v = 0; v < 3; v++) {
                    int pp = p+u-1, qq = q+v-1;
                    if (pp >= 0 && pp < 8 && qq >= 0 && qq < 8)
                        r += wc[u*3+v] * spc[pp*8+qq];
                }
            dst[b << 6] = __float2half(r);
        }
    }
}

// ---------------- fp16 mma.sync GEMM (B input half) -------------------------
// D[M x NCOL] = W[M,256] @ Y (+bias), Y stored [c][col] half. CTA 128x128.
#define AST 12
#define BST 136
template<bool HOUT>
__global__ __launch_bounds__(256) void mma_gemm(
    const float* __restrict__ W, const float* __restrict__ bias,
    const __half* __restrict__ Bm,
    void* __restrict__ out4, void* __restrict__ out8, int OD)
{
    __shared__ uint32_t As[2][128*AST];
    __shared__ uint32_t Bs[2][8*BST];
    int tid = threadIdx.x, lane = tid & 31, wid = tid >> 5;
    int warpM = wid & 1, warpN = wid >> 1;
    int mrow0 = blockIdx.x * 128, col0 = blockIdx.y * 128;
    const float* Ap = W + (size_t)mrow0 * 256;

    int r     = tid >> 1;            // A loader: row 0..127
    int halfo = (tid & 1) * 8;       // k offset 0 or 8
    int bj    = tid >> 5;            // B loader: kpair 0..7
    int bcol  = lane * 4;            // 4 cols

    float acc[4][4][4];
#pragma unroll
    for (int mt = 0; mt < 4; mt++)
#pragma unroll
        for (int nt = 0; nt < 4; nt++)
#pragma unroll
            for (int i = 0; i < 4; i++) acc[mt][nt][i] = 0.f;

    // prologue: chunk 0 -> buf 0
    {
        float4 a0 = *(const float4*)(Ap + (size_t)r*256 + halfo);
        float4 a1 = *(const float4*)(Ap + (size_t)r*256 + halfo + 4);
        uint4 av;
        av.x = h2pack(a0.x, a0.y); av.y = h2pack(a0.z, a0.w);
        av.z = h2pack(a1.x, a1.y); av.w = h2pack(a1.z, a1.w);
        *(uint4*)&As[0][r*AST + (halfo >> 1)] = av;
        uint2 r0 = *(const uint2*)(Bm + (size_t)(2*bj  )*NCOL + col0 + bcol);
        uint2 r1 = *(const uint2*)(Bm + (size_t)(2*bj+1)*NCOL + col0 + bcol);
        __half2 e01 = *(__half2*)&r0.x, e23 = *(__half2*)&r0.y;
        __half2 o01 = *(__half2*)&r1.x, o23 = *(__half2*)&r1.y;
        uint4 bv;
        bv.x = h2u(__halves2half2(__low2half(e01),  __low2half(o01)));
        bv.y = h2u(__halves2half2(__high2half(e01), __high2half(o01)));
        bv.z = h2u(__halves2half2(__low2half(e23),  __low2half(o23)));
        bv.w = h2u(__halves2half2(__high2half(e23), __high2half(o23)));
        *(uint4*)&Bs[0][bj*BST + bcol] = bv;
    }
    __syncthreads();

    int rowA = warpM*64 + (lane >> 2);
    int rowB = warpN*32 + (lane >> 2);
    int kq   = lane & 3;

    for (int kc = 0; kc < 16; kc++) {
        int buf = kc & 1;
        float4 a0, a1;
        uint2 r0, r1;
        if (kc < 15) {
            const float* ap = Ap + (size_t)r*256 + (kc+1)*16 + halfo;
            a0 = *(const float4*)(ap);     a1 = *(const float4*)(ap + 4);
            r0 = *(const uint2*)(Bm + (size_t)((kc+1)*16 + 2*bj  )*NCOL + col0 + bcol);
            r1 = *(const uint2*)(Bm + (size_t)((kc+1)*16 + 2*bj+1)*NCOL + col0 + bcol);
        }
        {
            uint32_t af[4][4], bf[4][2];
#pragma unroll
            for (int mt = 0; mt < 4; mt++) {
                int row = rowA + mt*16;
                af[mt][0] = As[buf][row*AST + kq];
                af[mt][1] = As[buf][(row+8)*AST + kq];
                af[mt][2] = As[buf][row*AST + kq + 4];
                af[mt][3] = As[buf][(row+8)*AST + kq + 4];
            }
#pragma unroll
            for (int nt = 0; nt < 4; nt++) {
                int coln = rowB + nt*8;
                bf[nt][0] = Bs[buf][kq*BST + coln];
                bf[nt][1] = Bs[buf][(kq+4)*BST + coln];
            }
#pragma unroll
            for (int mt = 0; mt < 4; mt++)
#pragma unroll
                for (int nt = 0; nt < 4; nt++)
                    mma_m16n8k16h(acc[mt][nt], af[mt], bf[nt]);
        }
        if (kc < 15) {
            uint4 av;
            av.x = h2pack(a0.x, a0.y); av.y = h2pack(a0.z, a0.w);
            av.z = h2pack(a1.x, a1.y); av.w = h2pack(a1.z, a1.w);
            *(uint4*)&As[buf^1][r*AST + (halfo >> 1)] = av;
            __half2 e01 = *(__half2*)&r0.x, e23 = *(__half2*)&r0.y;
            __half2 o01 = *(__half2*)&r1.x, o23 = *(__half2*)&r1.y;
            uint4 bv;
            bv.x = h2u(__halves2half2(__low2half(e01),  __low2half(o01)));
            bv.y = h2u(__halves2half2(__high2half(e01), __high2half(o01)));
            bv.z = h2u(__halves2half2(__low2half(e23),  __low2half(o23)));
            bv.w = h2u(__halves2half2(__high2half(e23), __high2half(o23)));
            *(uint4*)&Bs[buf^1][bj*BST + bcol] = bv;
        }
        __syncthreads();
    }

#pragma unroll
    for (int mt = 0; mt < 4; mt++) {
        int m0 = mrow0 + warpM*64 + mt*16 + (lane >> 2);
        float bv0 = bias[m0], bv1 = bias[m0 + 8];
#pragma unroll
        for (int nt = 0; nt < 4; nt++) {
            int coln = col0 + warpN*32 + nt*8 + (lane & 3)*2;
            float2 v0 = make_float2(acc[mt][nt][0] + bv0, acc[mt][nt][1] + bv0);
            float2 v1 = make_float2(acc[mt][nt][2] + bv1, acc[mt][nt][3] + bv1);
            if (coln < COL8_BASE) {
                int t0 = coln >> 4, s = coln & 15;
                if (HOUT) {
                    __half* o4 = (__half*)out4;
                    *(uint32_t*)(o4 + ((size_t)t0*OD + m0    )*16 + s) = h2pack(v0.x, v0.y);
                    *(uint32_t*)(o4 + ((size_t)t0*OD + m0 + 8)*16 + s) = h2pack(v1.x, v1.y);
                } else {
                    float* o4 = (float*)out4;
                    *(float2*)(o4 + ((size_t)t0*OD + m0    )*16 + s) = v0;
                    *(float2*)(o4 + ((size_t)t0*OD + m0 + 8)*16 + s) = v1;
                }
            } else {
                int t0 = (coln - COL8_BASE) >> 6, s = coln & 63;
                if (HOUT) {
                    __half* o8 = (__half*)out8;
                    *(uint32_t*)(o8 + ((size_t)t0*OD + m0    )*64 + s) = h2pack(v0.x, v0.y);
                    *(uint32_t*)(o8 + ((size_t)t0*OD + m0 + 8)*64 + s) = h2pack(v1.x, v1.y);
                } else {
                    float* o8 = (float*)out8;
                    *(float2*)(o8 + ((size_t)t0*OD + m0    )*64 + s) = v0;
                    *(float2*)(o8 + ((size_t)t0*OD + m0 + 8)*64 + s) = v1;
                }
            }
        }
    }
}

// ---------------- stage 3a: attention K=8 (tensor cores, half in/out) -------
__global__ __launch_bounds__(128) void attn8_mma(
    const __half* __restrict__ q8, const float* __restrict__ pew,
    const float* __restrict__ peb, __half* __restrict__ oall)
{
    extern __shared__ float sm8[];
    float* sqkv = sm8;                 // [128][68] (tf32 bits)
    float* sSO  = sm8 + 128*68;        // [64][68]
    float* swt  = sSO + 64*68;         // [64][10]
    uint32_t* uq = (uint32_t*)sqkv;
    uint32_t* uS = (uint32_t*)sSO;
    int t = blockIdx.x, h = blockIdx.y, tid = threadIdx.x;
    int lane = tid & 31, w = tid >> 5, r = lane >> 2, qd = lane & 3;

    const uint4* src = (const uint4*)(q8 + ((size_t)t*512 + h*128)*64);
    for (int i4 = tid; i4 < 1024; i4 += 128) {
        uint4 raw = src[i4];
        int row = i4 >> 3, c8 = (i4 & 7) << 3;
        const __half2* hp = (const __half2*)&raw;
        uint32_t* p = &uq[row*68 + c8];
#pragma unroll
        for (int j = 0; j < 4; j++) {
            float2 f = __half22float2(hp[j]);
            p[2*j]   = f2tf32(f.x);
            p[2*j+1] = f2tf32(f.y);
        }
    }
    for (int i = tid; i < 576; i += 128) {
        int ch = i / 9, k = i - ch*9;
        swt[ch*10 + k] = pew[(h*64+ch)*9 + k];
    }
    if (tid < 64) swt[tid*10+9] = peb[h*64 + tid];
    __syncthreads();

    int n0 = w*16 + r;
    float accS[8][4];
#pragma unroll
    for (int mt = 0; mt < 8; mt++)
#pragma unroll
        for (int j = 0; j < 4; j++) accS[mt][j] = 0.f;
#pragma unroll
    for (int ks = 0; ks < 4; ks++) {
        int d0 = ks*8 + qd;
        uint32_t av[4] = { uq[d0*68 + n0], uq[d0*68 + n0 + 8],
                           uq[(d0+4)*68 + n0], uq[(d0+4)*68 + n0 + 8] };
#pragma unroll
        for (int mt = 0; mt < 8; mt++) {
            uint32_t bv[2] = { uq[(32+d0)*68 + mt*8 + r], uq[(36+d0)*68 + mt*8 + r] };
            mma_m16n8k8(accS[mt], av, bv);
        }
    }
    const float SCALE = 0.17677669529663687f;
    float mx1 = -1e30f, mx2 = -1e30f;
#pragma unroll
    for (int mt = 0; mt < 8; mt++) {
        accS[mt][0] *= SCALE; accS[mt][1] *= SCALE; accS[mt][2] *= SCALE; accS[mt][3] *= SCALE;
        mx1 = fmaxf(mx1, fmaxf(accS[mt][0], accS[mt][1]));
        mx2 = fmaxf(mx2, fmaxf(accS[mt][2], accS[mt][3]));
    }
    mx1 = fmaxf(mx1, __shfl_xor_sync(~0u, mx1, 1)); mx1 = fmaxf(mx1, __shfl_xor_sync(~0u, mx1, 2));
    mx2 = fmaxf(mx2, __shfl_xor_sync(~0u, mx2, 1)); mx2 = fmaxf(mx2, __shfl_xor_sync(~0u, mx2, 2));
    float s1 = 0.f, s2 = 0.f;
#pragma unroll
    for (int mt = 0; mt < 8; mt++) {
        accS[mt][0] = __expf(accS[mt][0]-mx1); accS[mt][1] = __expf(accS[mt][1]-mx1);
        accS[mt][2] = __expf(accS[mt][2]-mx2); accS[mt][3] = __expf(accS[mt][3]-mx2);
        s1 += accS[mt][0] + accS[mt][1];
        s2 += accS[mt][2] + accS[mt][3];
    }
    s1 += __shfl_xor_sync(~0u, s1, 1); s1 += __shfl_xor_sync(~0u, s1, 2);
    s2 += __shfl_xor_sync(~0u, s2, 1); s2 += __shfl_xor_sync(~0u, s2, 2);
    float inv1 = 1.f/s1, inv2 = 1.f/s2;
#pragma unroll
    for (int mt = 0; mt < 8; mt++) {
        int m = mt*8 + 2*qd;
        uS[n0*68 + m]       = f2tf32(accS[mt][0]*inv1);
        uS[n0*68 + m+1]     = f2tf32(accS[mt][1]*inv1);
        uS[(n0+8)*68 + m]   = f2tf32(accS[mt][2]*inv2);
        uS[(n0+8)*68 + m+1] = f2tf32(accS[mt][3]*inv2);
    }
    __syncwarp();

    float accO[8][4];
#pragma unroll
    for (int nt = 0; nt < 8; nt++)
#pragma unroll
        for (int j = 0; j < 4; j++) accO[nt][j] = 0.f;
#pragma unroll
    for (int ks = 0; ks < 8; ks++) {
        int m0 = ks*8 + qd;
        uint32_t av[4] = { uS[n0*68 + m0], uS[(n0+8)*68 + m0],
                           uS[n0*68 + m0+4], uS[(n0+8)*68 + m0+4] };
#pragma unroll
        for (int nt = 0; nt < 8; nt++) {
            uint32_t bv[2] = { uq[(64+nt*8+r)*68 + m0], uq[(64+nt*8+r)*68 + m0+4] };
            mma_m16n8k8(accO[nt], av, bv);
        }
    }
    __syncthreads();
#pragma unroll
    for (int nt = 0; nt < 8; nt++) {
        int dd = nt*8 + 2*qd;
        sSO[dd*68 + n0]       = accO[nt][0];
        sSO[(dd+1)*68 + n0]   = accO[nt][1];
        sSO[dd*68 + n0+8]     = accO[nt][2];
        sSO[(dd+1)*68 + n0+8] = accO[nt][3];
    }
    __syncthreads();
    int n = (tid & 31) + ((w & 1) << 5);
    int p = n >> 3, qn = n & 7;
    int ddb = (w >> 1) * 32;
    __half* ob = oall + COL8_BASE + (size_t)t*64 + n;
#pragma unroll 4
    for (int i = 0; i < 32; i++) {
        int dd = ddb + i;
        const float* wt = &swt[dd*10];
        float cv = sSO[dd*68 + n] + wt[9];
        const uint32_t* vr = &uq[(64+dd)*68];
#pragma unroll
        for (int u = 0; u < 3; u++) {
            int pp = p+u-1;
            if ((unsigned)pp < 8u)
#pragma unroll
                for (int v = 0; v < 3; v++) {
                    int qq = qn+v-1;
                    if ((unsigned)qq < 8u)
                        cv += wt[u*3+v] * __uint_as_float(vr[pp*8+qq]);
                }
        }
        ob[(size_t)(h*64+dd)*NCOL] = __float2half(cv);
    }
}

// ---------------- stage 3b: attention K=4 (scalar, half in/out) -------------
__global__ __launch_bounds__(128) void attn4_scalar(
    const __half* __restrict__ qkv, const float* __restrict__ pew,
    const float* __restrict__ peb, __half* __restrict__ oall)
{
    __shared__ float sqkv[128*17];
    __shared__ float satt[16*17];
    int t = blockIdx.x, h = blockIdx.y, tid = threadIdx.x;
    const uint4* src = (const uint4*)(qkv + ((size_t)t*512 + h*128)*16);
    for (int i4 = tid; i4 < 256; i4 += 128) {
        uint4 raw = src[i4];
        int row = i4 >> 1, c8 = (i4 & 1) << 3;
        const __half2* hp = (const __half2*)&raw;
        float* p = &sqkv[row*17 + c8];
#pragma unroll
        for (int j = 0; j < 4; j++) {
            float2 f = __half22float2(hp[j]);
            p[2*j] = f.x; p[2*j+1] = f.y;
        }
    }
    __syncthreads();
    const float scale = 0.17677669529663687f;
    for (int idx = tid; idx < 256; idx += 128) {
        int m = idx & 15, n = idx >> 4;
        float d = 0.f;
#pragma unroll
        for (int dd = 0; dd < 32; dd++)
            d += sqkv[dd*17 + n] * sqkv[(32+dd)*17 + m];
        satt[n*17 + m] = d * scale;
    }
    __syncthreads();
    if (tid < 16) {
        float* row = &satt[tid*17];
        float mx = -1e30f;
#pragma unroll
        for (int m = 0; m < 16; m++) mx = fmaxf(mx, row[m]);
        float smv = 0.f;
#pragma unroll
        for (int m = 0; m < 16; m++) { float e = __expf(row[m]-mx); row[m] = e; smv += e; }
        float inv = 1.f/smv;
#pragma unroll
        for (int m = 0; m < 16; m++) row[m] *= inv;
    }
    __syncthreads();
    for (int idx = tid; idx < 1024; idx += 128) {
        int n = idx & 15, d = idx >> 4;
        const float* vrow = &sqkv[(64+d)*17];
        const float* arow = &satt[n*17];
        float acc = 0.f;
#pragma unroll
        for (int m = 0; m < 16; m++) acc += vrow[m]*arow[m];
        int c = h*64 + d;
        int p = n >> 2, q = n & 3;
        float r = acc + peb[c];
        const float* wc = pew + c*9;
#pragma unroll
        for (int u = 0; u < 3; u++) {
            int pp = p+u-1;
            if ((unsigned)pp < 4u)
#pragma unroll
                for (int v = 0; v < 3; v++) {
                    int qq = q+v-1;
                    if ((unsigned)qq < 4u)
                        r += wc[u*3+v] * vrow[pp*4+qq];
                }
        }
        oall[(size_t)c*NCOL + t*16 + n] = __float2half(r);
    }
}

// ---------------- stage 5: gather-fold + final average ----------------------
__global__ void combine_kernel(const float* __restrict__ x,
                               const float* __restrict__ a4,
                               const float* __restrict__ a8,
                               float* __restrict__ out)
{
    int idx = blockIdx.x*256 + threadIdx.x;
    if (idx >= N_*C_*H_*H_) return;
    int w = idx & 63;
    int h = (idx >> 6) & 63;
    int c = (idx >> 12) & 255;
    int n = idx >> 20;
    float xv = x[idx];
    {
        int p = h & 3, lh = h >> 2, q = w & 3, lw = w >> 2;
        xv += a4[(size_t)n*(256*16*256) + ((c*4+p)*4+q)*256 + lh*16 + lw];
    }
    float v8 = 0.f; int cnt = 0;
    int l1h = h >> 2, l1w = w >> 2;
#pragma unroll
    for (int dh = 0; dh < 2; dh++) {
        int lh = l1h - dh;
        if (lh < 0 || lh > 14) continue;
        int p = h - 4*lh;
#pragma unroll
        for (int dw = 0; dw < 2; dw++) {
            int lw = l1w - dw;
            if (lw < 0 || lw > 14) continue;
            int q = w - 4*lw;
            v8 += a8[(size_t)n*(256*64*225) + ((c*8+p)*8+q)*225 + lh*15 + lw];
            cnt++;
        }
    }
    out[idx] = (xv + v8 * (1.f/(float)cnt)) * (1.f/3.f);
}

// ---------------------------------------------------------------------------
extern "C" void kernel_launch(void* const* d_in, const int* in_sizes, int n_in,
                              void* d_out, int out_size)
{
    const float* x     = (const float*)d_in[0];
    const float* qkvw  = (const float*)d_in[1];
    const float* qkvb  = (const float*)d_in[2];
    const float* projw = (const float*)d_in[3];
    const float* projb = (const float*)d_in[4];
    const float* apew  = (const float*)d_in[5];
    const float* apeb  = (const float*)d_in[6];
    const float* dpew  = (const float*)d_in[7];
    const float* dpeb  = (const float*)d_in[8];
    float* out = (float*)d_out;

    void *yh, *oh, *q4h, *q8h, *a4v, *a8v;
    cudaGetSymbolAddress(&yh,  g_yh);
    cudaGetSymbolAddress(&oh,  g_oh);
    cudaGetSymbolAddress(&q4h, g_q4h);
    cudaGetSymbolAddress(&q8h, g_q8h);
    cudaGetSymbolAddress(&a4v, g_a4);
    cudaGetSymbolAddress(&a8v, g_a8);
    float* a4 = (float*)a4v;
    float* a8 = (float*)a8v;

    int attn8_smem = (128*68 + 64*68 + 64*10) * sizeof(float);
    cudaFuncSetAttribute(attn8_mma, cudaFuncAttributeMaxDynamicSharedMemorySize, attn8_smem);

    pool4_kernel<<<dim3(16, 8, 16), 256>>>(x, dpew, dpeb, (__half*)yh);
    pool8_kernel<<<dim3(15, 8, 64), 256>>>(x, dpew, dpeb, (__half*)yh);

    mma_gemm<true><<<dim3(4, NCOL/128), 256>>>(qkvw, qkvb, (const __half*)yh, q4h, q8h, 512);

    attn4_scalar<<<dim3(2048, 4), 128>>>((const __half*)q4h, apew, apeb, (__half*)oh);
    attn8_mma<<<dim3(1800, 4), 128, attn8_smem>>>((const __half*)q8h, apew, apeb, (__half*)oh);

    mma_gemm<false><<<dim3(2, NCOL/128), 256>>>(projw, projb, (const __half*)oh, a4, a8, 256);

    combine_kernel<<<(N_*C_*H_*H_ + 255)/256, 256>>>(x, a4, a8, out);
}